// round 12
// baseline (speedup 1.0000x reference)
#include <cuda_runtime.h>
#include <cuda_bf16.h>
#include <cuda_fp16.h>
#include <cstdint>

#define NPTS 500000
#define NCLU 40000
#define KRAW 91
#define DOUT 128
#define NTILES 3907          // ceil(500000/128)
#define SUMS_STRIDE 96
#define EPS 1e-5f
#define SLOPE 0.1f

// ---- smem layout (bytes) ----
#define ASTRB 160            // A chunk row stride: 40 fp32
#define ABUF 20480           // one A chunk: 128 x 160B
#define BOFF 40960           // B region start
#define BSTRB 80             // B row stride: 40 bf16
#define BCHUNK 20480         // per-chunk: hi 10240 + lo 10240
#define SMEM_BYTES 102400    // 2 A bufs + 3 B chunks
#define TSTR 136             // fp32 T stride (544 B/row)

// ---------------- device scratch ----------------
__device__ __align__(16) float g_sums[2ull * NCLU * SUMS_STRIDE];
__device__ __align__(16) float g_hc[2ull * NCLU * DOUT];
__device__ __align__(16) __half g_hh[(size_t)NPTS * DOUT];
__device__ int g_cs[NPTS];
__device__ __align__(16) __nv_bfloat16 g_Wb2[2][3][2][128 * 40];
__device__ float g_bnsum[DOUT];
__device__ float g_bnsq[DOUT];
__device__ float g_scale[DOUT];
__device__ float g_shift[DOUT];
__device__ int   g_maskmode;

// ---------------- PTX helpers ----------------
__device__ __forceinline__ uint32_t smem_u32(const void* p) {
    uint32_t a;
    asm("{ .reg .u64 t; cvta.to.shared.u64 t, %1; cvt.u32.u64 %0, t; }" : "=r"(a) : "l"(p));
    return a;
}
__device__ __forceinline__ void cpa16(uint32_t dst, const void* src, uint32_t sz) {
    asm volatile("cp.async.cg.shared.global [%0], [%1], 16, %2;"
                 :: "r"(dst), "l"(src), "r"(sz) : "memory");
}
__device__ __forceinline__ void cpa_commit() {
    asm volatile("cp.async.commit_group;" ::: "memory");
}
template<int N> __device__ __forceinline__ void cpa_wait() {
    asm volatile("cp.async.wait_group %0;" :: "n"(N) : "memory");
}
__device__ __forceinline__ void ldsm4(uint32_t* r, uint32_t addr) {
    asm volatile("ldmatrix.sync.aligned.m8n8.x4.shared.b16 {%0,%1,%2,%3}, [%4];"
                 : "=r"(r[0]), "=r"(r[1]), "=r"(r[2]), "=r"(r[3]) : "r"(addr));
}
__device__ __forceinline__ void mma_bf16(float* d, const uint32_t* a, uint32_t b0, uint32_t b1) {
    asm volatile("mma.sync.aligned.m16n8k16.row.col.f32.bf16.bf16.f32 "
                 "{%0,%1,%2,%3}, {%4,%5,%6,%7}, {%8,%9}, {%0,%1,%2,%3};"
                 : "+f"(d[0]), "+f"(d[1]), "+f"(d[2]), "+f"(d[3])
                 : "r"(a[0]), "r"(a[1]), "r"(a[2]), "r"(a[3]), "r"(b0), "r"(b1));
}
__device__ __forceinline__ void red4(float* p, float a, float b, float c, float d) {
    asm volatile("red.global.add.v4.f32 [%0], {%1, %2, %3, %4};"
                 :: "l"(p), "f"(a), "f"(b), "f"(c), "f"(d) : "memory");
}
__device__ __forceinline__ void split_pair(float f0, float f1, uint32_t& hi, uint32_t& lo) {
    asm("cvt.rn.bf16x2.f32 %0, %1, %2;" : "=r"(hi) : "f"(f1), "f"(f0));
    float h0 = __uint_as_float(hi << 16);
    float h1 = __uint_as_float(hi & 0xFFFF0000u);
    asm("cvt.rn.bf16x2.f32 %0, %1, %2;" : "=r"(lo) : "f"(f1 - h1), "f"(f0 - h0));
}
__device__ __forceinline__ int get_fg(const void* m, int i, int mode) {
    if (mode == 0) return ((const unsigned char*)m)[i] != 0;
    if (mode == 1) return ((const float*)m)[i] != 0.0f;
    return ((const int*)m)[i] != 0;
}

// ---------------- 0: merged prep ----------------
__global__ void prep_all_kernel(const unsigned char* __restrict__ mask,
                                const float* __restrict__ W) {
    int tid = threadIdx.x;
    size_t gid = (size_t)blockIdx.x * 256 + tid;

    if (blockIdx.x == 0) {
        __shared__ int s1, s3;
        if (tid == 0) { s1 = 0; s3 = 0; }
        __syncthreads();
        int o1 = 0, o3 = 0;
        for (int i = tid; i < 16384; i += 256) { o1 |= mask[i * 4 + 1]; o3 |= mask[i * 4 + 3]; }
        atomicOr(&s1, o1); atomicOr(&s3, o3);
        __syncthreads();
        if (tid == 0) g_maskmode = s1 ? 0 : (s3 ? 1 : 2);
    }

    const size_t n4 = (size_t)2 * NCLU * SUMS_STRIDE / 4;
    float4 z = make_float4(0.f, 0.f, 0.f, 0.f);
    if (gid < n4) reinterpret_cast<float4*>(g_sums)[gid] = z;
    if (gid < 32) reinterpret_cast<float4*>(g_bnsum)[gid] = z;
    else if (gid < 64) reinterpret_cast<float4*>(g_bnsq)[gid - 32] = z;

    const int total = 2 * 3 * 2 * 128 * 40;
    if (gid < (size_t)total) {
        int t = (int)gid;
        int half = t / 30720;
        int rem = t - half * 30720;
        int c = rem / 10240;
        int rem2 = rem - c * 10240;
        int hl = rem2 / 5120;
        int r = rem2 - hl * 5120;
        int n = r / 40, kk = r - n * 40;
        int k = c * 32 + kk;
        float v = (kk < 32 && k < KRAW) ? W[(size_t)n * 182 + half * KRAW + k] : 0.f;
        if (hl == 0) {
            g_Wb2[half][c][0][r] = __float2bfloat16(v);
        } else {
            __nv_bfloat16 hi = __float2bfloat16(v);
            g_Wb2[half][c][1][r] = __float2bfloat16(v - __bfloat162float(hi));
        }
    }
}

// ---------------- 1: scatter (emits g_cs) ----------------
__global__ void scatter_kernel(const float* __restrict__ feat, const float* __restrict__ logit,
                               const float* __restrict__ pts, const float* __restrict__ proj,
                               const int* __restrict__ idx, const void* __restrict__ mask) {
    int i = blockIdx.x * blockDim.x + threadIdx.x;
    if (i >= NPTS) return;
    int mode = g_maskmode;
    int fg = get_fg(mask, i, mode);
    int cs = (fg ? 0 : NCLU) + idx[i];
    g_cs[i] = cs;

    float v[92];
    const float4* f4 = reinterpret_cast<const float4*>(feat + (size_t)i * 64);
#pragma unroll
    for (int j = 0; j < 16; ++j) {
        float4 t = f4[j];
        v[4*j] = t.x; v[4*j+1] = t.y; v[4*j+2] = t.z; v[4*j+3] = t.w;
    }
    const float4* l4 = reinterpret_cast<const float4*>(logit + (size_t)i * 20);
#pragma unroll
    for (int j = 0; j < 5; ++j) {
        float4 t = l4[j];
        v[64+4*j] = t.x; v[64+4*j+1] = t.y; v[64+4*j+2] = t.z; v[64+4*j+3] = t.w;
    }
    {
        float4 t = reinterpret_cast<const float4*>(pts + (size_t)i * 4)[0];
        v[84] = t.x; v[85] = t.y; v[86] = t.z; v[87] = t.w;
    }
    v[88] = proj[(size_t)i*3]; v[89] = proj[(size_t)i*3+1]; v[90] = proj[(size_t)i*3+2];
    v[91] = 1.0f;

    float* base = g_sums + (size_t)cs * SUMS_STRIDE;
#pragma unroll
    for (int j = 0; j < 23; ++j)
        red4(base + 4*j, v[4*j], v[4*j+1], v[4*j+2], v[4*j+3]);
}

// ---------------- shared mainloop pieces ----------------
template<bool SCALE>
__device__ __forceinline__ void compute_chunk(char* smem, uint32_t smb, int abuf_off, int bchunk,
                                              int wr, int wc, int lane,
                                              const float sv[4], float acc[64]) {
    char* abase = smem + abuf_off + (size_t)(wr * 32 + (lane >> 2)) * ASTRB + (lane & 3) * 8;
    uint32_t bbase = smb + BOFF + bchunk * BCHUNK
                   + (uint32_t)(wc * 64 + (lane & 7) + ((lane >> 4) & 1) * 8) * BSTRB
                   + ((lane >> 3) & 1) * 16;
#pragma unroll
    for (int ks = 0; ks < 2; ++ks) {
        uint32_t ah[2][4], al[2][4];
#pragma unroll
        for (int fr = 0; fr < 4; ++fr) {
            float2 u0 = *reinterpret_cast<float2*>(abase + fr * 8 * ASTRB + ks * 64);
            float2 u1 = *reinterpret_cast<float2*>(abase + fr * 8 * ASTRB + ks * 64 + 32);
            if (SCALE) {
                float s = sv[fr];
                u0.x *= s; u0.y *= s; u1.x *= s; u1.y *= s;
            }
            uint32_t hA, lA, hB, lB;
            split_pair(u0.x, u0.y, hA, lA);
            split_pair(u1.x, u1.y, hB, lB);
            int t = fr >> 1, rr = fr & 1;
            ah[t][rr] = hA; ah[t][2 + rr] = hB;
            al[t][rr] = lA; al[t][2 + rr] = lB;
        }
#pragma unroll
        for (int nb = 0; nb < 4; ++nb) {
            uint32_t bh[4], bl[4];
            uint32_t bo = (uint32_t)nb * 16 * BSTRB + ks * 32;
            ldsm4(bh, bbase + bo);
            ldsm4(bl, bbase + bo + 10240);
            float* c00 = acc + nb * 8;
            float* c01 = c00 + 4;
            float* c10 = acc + (4 + nb) * 8;
            float* c11 = c10 + 4;
            mma_bf16(c00, ah[0], bh[0], bh[1]); mma_bf16(c01, ah[0], bh[2], bh[3]);
            mma_bf16(c10, ah[1], bh[0], bh[1]); mma_bf16(c11, ah[1], bh[2], bh[3]);
            mma_bf16(c00, al[0], bh[0], bh[1]); mma_bf16(c01, al[0], bh[2], bh[3]);
            mma_bf16(c10, al[1], bh[0], bh[1]); mma_bf16(c11, al[1], bh[2], bh[3]);
            mma_bf16(c00, ah[0], bl[0], bl[1]); mma_bf16(c01, ah[0], bl[2], bl[3]);
            mma_bf16(c10, ah[1], bl[0], bl[1]); mma_bf16(c11, ah[1], bl[2], bl[3]);
        }
    }
}

__device__ __forceinline__ void frags_to_T(float* T, int wid, int lane, const float acc[64]) {
    int wr = wid & 3, wc = wid >> 2;
    int rbase = wr * 32 + (lane >> 2);
    int cb = wc * 64 + 2 * (lane & 3);
#pragma unroll
    for (int mrow = 0; mrow < 2; ++mrow) {
        int r0 = rbase + mrow * 16;
#pragma unroll
        for (int nb = 0; nb < 4; ++nb) {
#pragma unroll
            for (int t = 0; t < 2; ++t) {
                const float* a4 = acc + ((mrow * 4 + nb) * 2 + t) * 4;
                int c = cb + nb * 16 + t * 8;
                *reinterpret_cast<float2*>(T + r0 * TSTR + c) = make_float2(a4[0], a4[1]);
                *reinterpret_cast<float2*>(T + (r0 + 8) * TSTR + c) = make_float2(a4[2], a4[3]);
            }
        }
    }
}

__device__ __forceinline__ void issue_B(uint32_t smb, int tid, int half) {
    const char* src = (const char*)&g_Wb2[half][0][0][0];
#pragma unroll
    for (int j = 0; j < 15; ++j) {
        int i = tid + 256 * j;
        cpa16(smb + BOFF + i * 16, src + i * 16, 16);
    }
}

// ---------------- 2: hc = W2 @ mean + b ----------------
__global__ __launch_bounds__(256, 2)
void hc_mma_kernel(const float* __restrict__ bias) {
    extern __shared__ __align__(16) char smem[];
    __shared__ float s_inv[128];
    uint32_t smb = smem_u32(smem);
    int tid = threadIdx.x, wid = tid >> 5, lane = tid & 31;
    int wr = wid & 3, wc = wid >> 2;
    int row0 = blockIdx.x * 128;
    const char* sbase = (const char*)g_sums + (size_t)row0 * 384;

    issue_B(smb, tid, 1);
#pragma unroll
    for (int j = 0; j < 4; ++j) {
        int i = tid + 256 * j, p = i >> 3, u = i & 7;
        cpa16(smb + p * ASTRB + u * 16, sbase + (size_t)p * 384 + u * 16, 16);
    }
    cpa_commit();
#pragma unroll
    for (int j = 0; j < 4; ++j) {
        int i = tid + 256 * j, p = i >> 3, u = i & 7;
        cpa16(smb + ABUF + p * ASTRB + u * 16, sbase + (size_t)p * 384 + 128 + u * 16, 16);
    }
    cpa_commit();

    if (tid < 128) {
        float c = g_sums[(size_t)(row0 + tid) * SUMS_STRIDE + 91];
        s_inv[tid] = (c > 0.f) ? 1.0f / c : 0.0f;
    }

    float acc[64];
#pragma unroll
    for (int j = 0; j < 64; ++j) acc[j] = 0.f;

    cpa_wait<1>();
    __syncthreads();
    float sv[4];
#pragma unroll
    for (int fr = 0; fr < 4; ++fr) sv[fr] = s_inv[wr * 32 + (lane >> 2) + fr * 8];

    compute_chunk<true>(smem, smb, 0, 0, wr, wc, lane, sv, acc);
    __syncthreads();
#pragma unroll
    for (int j = 0; j < 4; ++j) {
        int i = tid + 256 * j, p = i >> 3, u = i & 7;
        cpa16(smb + p * ASTRB + u * 16, sbase + (size_t)p * 384 + 256 + u * 16, 16);
    }
    cpa_commit();
    cpa_wait<1>();
    __syncthreads();
    compute_chunk<true>(smem, smb, ABUF, 1, wr, wc, lane, sv, acc);
    cpa_wait<0>();
    __syncthreads();
    compute_chunk<true>(smem, smb, 0, 2, wr, wc, lane, sv, acc);
    __syncthreads();

    float* T = reinterpret_cast<float*>(smem);
    frags_to_T(T, wid, lane, acc);
    __syncthreads();

    for (int i4 = tid; i4 < 4096; i4 += 256) {
        int p = i4 >> 5, c = (i4 & 31) * 4;
        float4 o = *reinterpret_cast<float4*>(T + p * TSTR + c);
        o.x += __ldg(bias + c + 0);
        o.y += __ldg(bias + c + 1);
        o.z += __ldg(bias + c + 2);
        o.w += __ldg(bias + c + 3);
        reinterpret_cast<float4*>(g_hc + (size_t)(row0 + p) * DOUT)[i4 & 31] = o;
    }
}

// ---------------- 3: main GEMM (profiled) ----------------
__global__ __launch_bounds__(256, 2)
void main_mma_kernel(const float* __restrict__ feat, const float* __restrict__ logit,
                     const float* __restrict__ pts, const float* __restrict__ proj) {
    extern __shared__ __align__(16) char smem[];
    uint32_t smb = smem_u32(smem);
    int tid = threadIdx.x, wid = tid >> 5, lane = tid & 31;
    int wr = wid & 3, wc = wid >> 2;
    int row0 = blockIdx.x * 128;

    // g0: B + A chunk0
    issue_B(smb, tid, 0);
#pragma unroll
    for (int j = 0; j < 4; ++j) {
        int i = tid + 256 * j, p = i >> 3, u = i & 7;
        int r = row0 + p;
        const char* s = (r < NPTS) ? (const char*)feat + (size_t)r * 256 + u * 16 : (const char*)feat;
        cpa16(smb + p * ASTRB + u * 16, s, (r < NPTS) ? 16u : 0u);
    }
    cpa_commit();
    // g1: A chunk1
#pragma unroll
    for (int j = 0; j < 4; ++j) {
        int i = tid + 256 * j, p = i >> 3, u = i & 7;
        int r = row0 + p;
        const char* s = (r < NPTS) ? (const char*)feat + (size_t)r * 256 + 128 + u * 16 : (const char*)feat;
        cpa16(smb + ABUF + p * ASTRB + u * 16, s, (r < NPTS) ? 16u : 0u);
    }
    cpa_commit();

    float acc[64];
#pragma unroll
    for (int j = 0; j < 64; ++j) acc[j] = 0.f;
    const float sv[4] = {1.f, 1.f, 1.f, 1.f};

    cpa_wait<1>();
    __syncthreads();
    compute_chunk<false>(smem, smb, 0, 0, wr, wc, lane, sv, acc);
    __syncthreads();

    // chunk2 into buf0: logit (5 units) + pts (1 unit) async; proj + zero tail scalar
#pragma unroll
    for (int j = 0; j < 3; ++j) {
        int i = tid + 256 * j, p = i / 6, u = i - p * 6;
        int r = row0 + p;
        const char* s;
        if (r < NPTS) s = (u < 5) ? (const char*)logit + (size_t)r * 80 + u * 16
                                  : (const char*)pts + (size_t)r * 16;
        else s = (const char*)feat;
        cpa16(smb + p * ASTRB + u * 16, s, (r < NPTS) ? 16u : 0u);
    }
    cpa_commit();
    {
        float* A0 = reinterpret_cast<float*>(smem);
#pragma unroll
        for (int j = 0; j < 4; ++j) {
            int i = tid + 256 * j, p = i >> 3, kk = i & 7;
            int r = row0 + p;
            float v = (kk < 3 && r < NPTS) ? proj[(size_t)r * 3 + kk] : 0.f;
            A0[p * 40 + 24 + kk] = v;
        }
    }
    cpa_wait<1>();
    __syncthreads();
    compute_chunk<false>(smem, smb, ABUF, 1, wr, wc, lane, sv, acc);
    cpa_wait<0>();
    __syncthreads();
    compute_chunk<false>(smem, smb, 0, 2, wr, wc, lane, sv, acc);
    __syncthreads();

    float* T = reinterpret_cast<float*>(smem);
    frags_to_T(T, wid, lane, acc);
    __syncthreads();

    // cooperative hc add: cs loaded HERE (not mainloop-live); two batches of 8 LDG.128
    {
        int p0 = wid * 16;
        int rl = row0 + p0 + (lane & 15);
        int csl = (rl < NPTS) ? g_cs[rl] : 0;
#pragma unroll
        for (int half = 0; half < 2; ++half) {
            float4 hv[8];
#pragma unroll
            for (int it = 0; it < 8; ++it) {
                int cs = __shfl_sync(0xFFFFFFFFu, csl, half * 8 + it);
                hv[it] = reinterpret_cast<const float4*>(g_hc + (size_t)cs * DOUT)[lane];
            }
#pragma unroll
            for (int it = 0; it < 8; ++it) {
                int p = p0 + half * 8 + it;
                if (row0 + p < NPTS) {
                    float4* q = reinterpret_cast<float4*>(T + p * TSTR + 4 * lane);
                    float4 t = *q;
                    t.x += hv[it].x; t.y += hv[it].y; t.z += hv[it].z; t.w += hv[it].w;
                    *q = t;
                }
            }
        }
    }
    __syncthreads();

    // fused: g_hh store + BN partials in one T pass.
    // i4 & 31 is constant per thread -> each thread covers one 4-col group over 16 rows.
    {
        int rem = NPTS - row0;
        float4 s = make_float4(0.f, 0.f, 0.f, 0.f);
        float4 q = make_float4(0.f, 0.f, 0.f, 0.f);
        int c4 = tid & 31;
        for (int i4 = tid; i4 < 4096; i4 += 256) {
            int p = i4 >> 5;
            float4 o = *reinterpret_cast<float4*>(T + p * TSTR + c4 * 4);
            // tail rows are exact zeros in T -> contribute nothing
            s.x += o.x; s.y += o.y; s.z += o.z; s.w += o.w;
            q.x += o.x * o.x; q.y += o.y * o.y; q.z += o.z * o.z; q.w += o.w * o.w;
            if (p < rem) {
                __half2 h0 = __floats2half2_rn(o.x, o.y);
                __half2 h1 = __floats2half2_rn(o.z, o.w);
                uint2 st;
                st.x = *reinterpret_cast<uint32_t*>(&h0);
                st.y = *reinterpret_cast<uint32_t*>(&h1);
                reinterpret_cast<uint2*>(g_hh + ((size_t)(row0 + p) << 7))[c4] = st;
            }
        }
        int c = c4 * 4;
        atomicAdd(&g_bnsum[c + 0], s.x); atomicAdd(&g_bnsum[c + 1], s.y);
        atomicAdd(&g_bnsum[c + 2], s.z); atomicAdd(&g_bnsum[c + 3], s.w);
        atomicAdd(&g_bnsq[c + 0], q.x); atomicAdd(&g_bnsq[c + 1], q.y);
        atomicAdd(&g_bnsq[c + 2], q.z); atomicAdd(&g_bnsq[c + 3], q.w);
    }
}

// ---------------- 4: BN finalize ----------------
__global__ void bn_finalize_kernel(const float* __restrict__ gamma,
                                   const float* __restrict__ beta) {
    int d = threadIdx.x;
    const float invN = 1.0f / (float)NPTS;
    float mu = g_bnsum[d] * invN;
    float var = g_bnsq[d] * invN - mu * mu;
    if (var < 0.f) var = 0.f;
    float sc = gamma[d] * rsqrtf(var + EPS);
    g_scale[d] = sc;
    g_shift[d] = beta[d] - mu * sc;
}

// ---------------- 5: map: wide (8 halfs / thread) ----------------
__global__ __launch_bounds__(256) void map_kernel(float* __restrict__ out) {
    __shared__ float sc[DOUT], sh[DOUT];
    int tid = threadIdx.x;
    if (tid < DOUT) { sc[tid] = g_scale[tid]; sh[tid] = g_shift[tid]; }
    __syncthreads();
    size_t gid = (size_t)blockIdx.x * 256 + tid;     // over uint4 (8 halfs)
    int d = ((int)(gid & 15)) * 8;
    uint4 raw = reinterpret_cast<const uint4*>(g_hh)[gid];
    float2 f0 = __half22float2(*reinterpret_cast<__half2*>(&raw.x));
    float2 f1 = __half22float2(*reinterpret_cast<__half2*>(&raw.y));
    float2 f2 = __half22float2(*reinterpret_cast<__half2*>(&raw.z));
    float2 f3 = __half22float2(*reinterpret_cast<__half2*>(&raw.w));
    float4 r0, r1;
    float v;
    v = f0.x * sc[d + 0] + sh[d + 0]; r0.x = (v >= 0.f) ? v : SLOPE * v;
    v = f0.y * sc[d + 1] + sh[d + 1]; r0.y = (v >= 0.f) ? v : SLOPE * v;
    v = f1.x * sc[d + 2] + sh[d + 2]; r0.z = (v >= 0.f) ? v : SLOPE * v;
    v = f1.y * sc[d + 3] + sh[d + 3]; r0.w = (v >= 0.f) ? v : SLOPE * v;
    v = f2.x * sc[d + 4] + sh[d + 4]; r1.x = (v >= 0.f) ? v : SLOPE * v;
    v = f2.y * sc[d + 5] + sh[d + 5]; r1.y = (v >= 0.f) ? v : SLOPE * v;
    v = f3.x * sc[d + 6] + sh[d + 6]; r1.z = (v >= 0.f) ? v : SLOPE * v;
    v = f3.y * sc[d + 7] + sh[d + 7]; r1.w = (v >= 0.f) ? v : SLOPE * v;
    reinterpret_cast<float4*>(out)[gid * 2 + 0] = r0;
    reinterpret_cast<float4*>(out)[gid * 2 + 1] = r1;
}

// ---------------- launch ----------------
extern "C" void kernel_launch(void* const* d_in, const int* in_sizes, int n_in,
                              void* d_out, int out_size) {
    const float* points = (const float*)d_in[0];
    const float* proj   = (const float*)d_in[1];
    const float* feat   = (const float*)d_in[2];
    const float* logits = (const float*)d_in[3];
    const int*   idx    = (const int*)d_in[4];
    const void*  mask   = d_in[5];
    const float* W      = (const float*)d_in[6];
    const float* bias   = (const float*)d_in[7];
    const float* gamma  = (const float*)d_in[8];
    const float* beta   = (const float*)d_in[9];
    float* out = (float*)d_out;

    cudaFuncSetAttribute(hc_mma_kernel, cudaFuncAttributeMaxDynamicSharedMemorySize, SMEM_BYTES);
    cudaFuncSetAttribute(main_mma_kernel, cudaFuncAttributeMaxDynamicSharedMemorySize, SMEM_BYTES);

    prep_all_kernel<<<7500, 256>>>((const unsigned char*)mask, W);
    scatter_kernel<<<(NPTS + 255) / 256, 256>>>(feat, logits, points, proj, idx, mask);
    hc_mma_kernel<<<2 * NCLU / 128, 256, SMEM_BYTES>>>(bias);
    // launch 3 (profiled): main GEMM
    main_mma_kernel<<<NTILES, 256, SMEM_BYTES>>>(feat, logits, points, proj);
    bn_finalize_kernel<<<1, DOUT>>>(gamma, beta);
    map_kernel<<<31250, 256>>>(out);   // 8M uint4 / 256
}

// round 13
// speedup vs baseline: 4.1501x; 4.1501x over previous
#include <cuda_runtime.h>
#include <cuda_bf16.h>
#include <cuda_fp16.h>
#include <cstdint>

#define NPTS 500000
#define NCLU 40000
#define KRAW 91
#define DOUT 128
#define NTILES 3907          // ceil(500000/128)
#define SUMS_STRIDE 96
#define EPS 1e-5f
#define SLOPE 0.1f

// ---- smem layout (bytes) ----
#define ASTRB 160            // A chunk row stride: 40 fp32
#define ABUF 20480           // one A chunk: 128 x 160B
#define BOFF 40960           // B region start
#define BSTRB 80             // B row stride: 40 bf16
#define BCHUNK 20480         // per-chunk: hi 10240 + lo 10240
#define SMEM_BYTES 102400    // 2 A bufs + 3 B chunks
#define TSTR 136             // fp32 T stride (544 B/row)

// ---------------- device scratch ----------------
__device__ __align__(16) float g_sums[2ull * NCLU * SUMS_STRIDE];
__device__ __align__(16) float g_hc[2ull * NCLU * DOUT];
__device__ __align__(16) __half g_hh[(size_t)NPTS * DOUT];
__device__ int g_cs[NPTS];
__device__ __align__(16) __nv_bfloat16 g_Wb2[2][3][2][128 * 40];
__device__ float g_bnsum[DOUT];
__device__ float g_bnsq[DOUT];
__device__ float g_scale[DOUT];
__device__ float g_shift[DOUT];
__device__ int   g_maskmode;

// ---------------- PTX helpers ----------------
__device__ __forceinline__ uint32_t smem_u32(const void* p) {
    uint32_t a;
    asm("{ .reg .u64 t; cvta.to.shared.u64 t, %1; cvt.u32.u64 %0, t; }" : "=r"(a) : "l"(p));
    return a;
}
__device__ __forceinline__ void cpa16(uint32_t dst, const void* src, uint32_t sz) {
    asm volatile("cp.async.cg.shared.global [%0], [%1], 16, %2;"
                 :: "r"(dst), "l"(src), "r"(sz) : "memory");
}
__device__ __forceinline__ void cpa_commit() {
    asm volatile("cp.async.commit_group;" ::: "memory");
}
template<int N> __device__ __forceinline__ void cpa_wait() {
    asm volatile("cp.async.wait_group %0;" :: "n"(N) : "memory");
}
__device__ __forceinline__ void ldsm4(uint32_t* r, uint32_t addr) {
    asm volatile("ldmatrix.sync.aligned.m8n8.x4.shared.b16 {%0,%1,%2,%3}, [%4];"
                 : "=r"(r[0]), "=r"(r[1]), "=r"(r[2]), "=r"(r[3]) : "r"(addr));
}
__device__ __forceinline__ void mma_bf16(float* d, const uint32_t* a, uint32_t b0, uint32_t b1) {
    asm volatile("mma.sync.aligned.m16n8k16.row.col.f32.bf16.bf16.f32 "
                 "{%0,%1,%2,%3}, {%4,%5,%6,%7}, {%8,%9}, {%0,%1,%2,%3};"
                 : "+f"(d[0]), "+f"(d[1]), "+f"(d[2]), "+f"(d[3])
                 : "r"(a[0]), "r"(a[1]), "r"(a[2]), "r"(a[3]), "r"(b0), "r"(b1));
}
__device__ __forceinline__ void red4(float* p, float a, float b, float c, float d) {
    asm volatile("red.global.add.v4.f32 [%0], {%1, %2, %3, %4};"
                 :: "l"(p), "f"(a), "f"(b), "f"(c), "f"(d) : "memory");
}
__device__ __forceinline__ void split_pair(float f0, float f1, uint32_t& hi, uint32_t& lo) {
    asm("cvt.rn.bf16x2.f32 %0, %1, %2;" : "=r"(hi) : "f"(f1), "f"(f0));
    float h0 = __uint_as_float(hi << 16);
    float h1 = __uint_as_float(hi & 0xFFFF0000u);
    asm("cvt.rn.bf16x2.f32 %0, %1, %2;" : "=r"(lo) : "f"(f1 - h1), "f"(f0 - h0));
}
__device__ __forceinline__ int get_fg(const void* m, int i, int mode) {
    if (mode == 0) return ((const unsigned char*)m)[i] != 0;
    if (mode == 1) return ((const float*)m)[i] != 0.0f;
    return ((const int*)m)[i] != 0;
}

// ---------------- 0: merged prep ----------------
__global__ void prep_all_kernel(const unsigned char* __restrict__ mask,
                                const float* __restrict__ W) {
    int tid = threadIdx.x;
    size_t gid = (size_t)blockIdx.x * 256 + tid;

    if (blockIdx.x == 0) {
        __shared__ int s1, s3;
        if (tid == 0) { s1 = 0; s3 = 0; }
        __syncthreads();
        int o1 = 0, o3 = 0;
        for (int i = tid; i < 16384; i += 256) { o1 |= mask[i * 4 + 1]; o3 |= mask[i * 4 + 3]; }
        atomicOr(&s1, o1); atomicOr(&s3, o3);
        __syncthreads();
        if (tid == 0) g_maskmode = s1 ? 0 : (s3 ? 1 : 2);
    }

    const size_t n4 = (size_t)2 * NCLU * SUMS_STRIDE / 4;
    float4 z = make_float4(0.f, 0.f, 0.f, 0.f);
    if (gid < n4) reinterpret_cast<float4*>(g_sums)[gid] = z;
    if (gid < 32) reinterpret_cast<float4*>(g_bnsum)[gid] = z;
    else if (gid < 64) reinterpret_cast<float4*>(g_bnsq)[gid - 32] = z;

    const int total = 2 * 3 * 2 * 128 * 40;
    if (gid < (size_t)total) {
        int t = (int)gid;
        int half = t / 30720;
        int rem = t - half * 30720;
        int c = rem / 10240;
        int rem2 = rem - c * 10240;
        int hl = rem2 / 5120;
        int r = rem2 - hl * 5120;
        int n = r / 40, kk = r - n * 40;
        int k = c * 32 + kk;
        float v = (kk < 32 && k < KRAW) ? W[(size_t)n * 182 + half * KRAW + k] : 0.f;
        if (hl == 0) {
            g_Wb2[half][c][0][r] = __float2bfloat16(v);
        } else {
            __nv_bfloat16 hi = __float2bfloat16(v);
            g_Wb2[half][c][1][r] = __float2bfloat16(v - __bfloat162float(hi));
        }
    }
}

// ---------------- 1: scatter (emits g_cs) ----------------
__global__ void scatter_kernel(const float* __restrict__ feat, const float* __restrict__ logit,
                               const float* __restrict__ pts, const float* __restrict__ proj,
                               const int* __restrict__ idx, const void* __restrict__ mask) {
    int i = blockIdx.x * blockDim.x + threadIdx.x;
    if (i >= NPTS) return;
    int mode = g_maskmode;
    int fg = get_fg(mask, i, mode);
    int cs = (fg ? 0 : NCLU) + idx[i];
    g_cs[i] = cs;

    float v[92];
    const float4* f4 = reinterpret_cast<const float4*>(feat + (size_t)i * 64);
#pragma unroll
    for (int j = 0; j < 16; ++j) {
        float4 t = f4[j];
        v[4*j] = t.x; v[4*j+1] = t.y; v[4*j+2] = t.z; v[4*j+3] = t.w;
    }
    const float4* l4 = reinterpret_cast<const float4*>(logit + (size_t)i * 20);
#pragma unroll
    for (int j = 0; j < 5; ++j) {
        float4 t = l4[j];
        v[64+4*j] = t.x; v[64+4*j+1] = t.y; v[64+4*j+2] = t.z; v[64+4*j+3] = t.w;
    }
    {
        float4 t = reinterpret_cast<const float4*>(pts + (size_t)i * 4)[0];
        v[84] = t.x; v[85] = t.y; v[86] = t.z; v[87] = t.w;
    }
    v[88] = proj[(size_t)i*3]; v[89] = proj[(size_t)i*3+1]; v[90] = proj[(size_t)i*3+2];
    v[91] = 1.0f;

    float* base = g_sums + (size_t)cs * SUMS_STRIDE;
#pragma unroll
    for (int j = 0; j < 23; ++j)
        red4(base + 4*j, v[4*j], v[4*j+1], v[4*j+2], v[4*j+3]);
}

// ---------------- shared mainloop pieces ----------------
template<bool SCALE>
__device__ __forceinline__ void compute_chunk(char* smem, uint32_t smb, int abuf_off, int bchunk,
                                              int wr, int wc, int lane,
                                              const float sv[4], float acc[64]) {
    char* abase = smem + abuf_off + (size_t)(wr * 32 + (lane >> 2)) * ASTRB + (lane & 3) * 8;
    uint32_t bbase = smb + BOFF + bchunk * BCHUNK
                   + (uint32_t)(wc * 64 + (lane & 7) + ((lane >> 4) & 1) * 8) * BSTRB
                   + ((lane >> 3) & 1) * 16;
#pragma unroll
    for (int ks = 0; ks < 2; ++ks) {
        uint32_t ah[2][4], al[2][4];
#pragma unroll
        for (int fr = 0; fr < 4; ++fr) {
            float2 u0 = *reinterpret_cast<float2*>(abase + fr * 8 * ASTRB + ks * 64);
            float2 u1 = *reinterpret_cast<float2*>(abase + fr * 8 * ASTRB + ks * 64 + 32);
            if (SCALE) {
                float s = sv[fr];
                u0.x *= s; u0.y *= s; u1.x *= s; u1.y *= s;
            }
            uint32_t hA, lA, hB, lB;
            split_pair(u0.x, u0.y, hA, lA);
            split_pair(u1.x, u1.y, hB, lB);
            int t = fr >> 1, rr = fr & 1;
            ah[t][rr] = hA; ah[t][2 + rr] = hB;
            al[t][rr] = lA; al[t][2 + rr] = lB;
        }
#pragma unroll
        for (int nb = 0; nb < 4; ++nb) {
            uint32_t bh[4], bl[4];
            uint32_t bo = (uint32_t)nb * 16 * BSTRB + ks * 32;
            ldsm4(bh, bbase + bo);
            ldsm4(bl, bbase + bo + 10240);
            float* c00 = acc + nb * 8;
            float* c01 = c00 + 4;
            float* c10 = acc + (4 + nb) * 8;
            float* c11 = c10 + 4;
            mma_bf16(c00, ah[0], bh[0], bh[1]); mma_bf16(c01, ah[0], bh[2], bh[3]);
            mma_bf16(c10, ah[1], bh[0], bh[1]); mma_bf16(c11, ah[1], bh[2], bh[3]);
            mma_bf16(c00, al[0], bh[0], bh[1]); mma_bf16(c01, al[0], bh[2], bh[3]);
            mma_bf16(c10, al[1], bh[0], bh[1]); mma_bf16(c11, al[1], bh[2], bh[3]);
            mma_bf16(c00, ah[0], bl[0], bl[1]); mma_bf16(c01, ah[0], bl[2], bl[3]);
            mma_bf16(c10, ah[1], bl[0], bl[1]); mma_bf16(c11, ah[1], bl[2], bl[3]);
        }
    }
}

__device__ __forceinline__ void frags_to_T(float* T, int wid, int lane, const float acc[64]) {
    int wr = wid & 3, wc = wid >> 2;
    int rbase = wr * 32 + (lane >> 2);
    int cb = wc * 64 + 2 * (lane & 3);
#pragma unroll
    for (int mrow = 0; mrow < 2; ++mrow) {
        int r0 = rbase + mrow * 16;
#pragma unroll
        for (int nb = 0; nb < 4; ++nb) {
#pragma unroll
            for (int t = 0; t < 2; ++t) {
                const float* a4 = acc + ((mrow * 4 + nb) * 2 + t) * 4;
                int c = cb + nb * 16 + t * 8;
                *reinterpret_cast<float2*>(T + r0 * TSTR + c) = make_float2(a4[0], a4[1]);
                *reinterpret_cast<float2*>(T + (r0 + 8) * TSTR + c) = make_float2(a4[2], a4[3]);
            }
        }
    }
}

__device__ __forceinline__ void issue_B(uint32_t smb, int tid, int half) {
    const char* src = (const char*)&g_Wb2[half][0][0][0];
#pragma unroll
    for (int j = 0; j < 15; ++j) {
        int i = tid + 256 * j;
        cpa16(smb + BOFF + i * 16, src + i * 16, 16);
    }
}

// ---------------- 2: hc = W2 @ mean + b ----------------
__global__ __launch_bounds__(256, 2)
void hc_mma_kernel(const float* __restrict__ bias) {
    extern __shared__ __align__(16) char smem[];
    __shared__ float s_inv[128];
    uint32_t smb = smem_u32(smem);
    int tid = threadIdx.x, wid = tid >> 5, lane = tid & 31;
    int wr = wid & 3, wc = wid >> 2;
    int row0 = blockIdx.x * 128;
    const char* sbase = (const char*)g_sums + (size_t)row0 * 384;

    issue_B(smb, tid, 1);
#pragma unroll
    for (int j = 0; j < 4; ++j) {
        int i = tid + 256 * j, p = i >> 3, u = i & 7;
        cpa16(smb + p * ASTRB + u * 16, sbase + (size_t)p * 384 + u * 16, 16);
    }
    cpa_commit();
#pragma unroll
    for (int j = 0; j < 4; ++j) {
        int i = tid + 256 * j, p = i >> 3, u = i & 7;
        cpa16(smb + ABUF + p * ASTRB + u * 16, sbase + (size_t)p * 384 + 128 + u * 16, 16);
    }
    cpa_commit();

    if (tid < 128) {
        float c = g_sums[(size_t)(row0 + tid) * SUMS_STRIDE + 91];
        s_inv[tid] = (c > 0.f) ? 1.0f / c : 0.0f;
    }

    float acc[64];
#pragma unroll
    for (int j = 0; j < 64; ++j) acc[j] = 0.f;

    cpa_wait<1>();
    __syncthreads();
    float sv[4];
#pragma unroll
    for (int fr = 0; fr < 4; ++fr) sv[fr] = s_inv[wr * 32 + (lane >> 2) + fr * 8];

    compute_chunk<true>(smem, smb, 0, 0, wr, wc, lane, sv, acc);
    __syncthreads();
#pragma unroll
    for (int j = 0; j < 4; ++j) {
        int i = tid + 256 * j, p = i >> 3, u = i & 7;
        cpa16(smb + p * ASTRB + u * 16, sbase + (size_t)p * 384 + 256 + u * 16, 16);
    }
    cpa_commit();
    cpa_wait<1>();
    __syncthreads();
    compute_chunk<true>(smem, smb, ABUF, 1, wr, wc, lane, sv, acc);
    cpa_wait<0>();
    __syncthreads();
    compute_chunk<true>(smem, smb, 0, 2, wr, wc, lane, sv, acc);
    __syncthreads();

    float* T = reinterpret_cast<float*>(smem);
    frags_to_T(T, wid, lane, acc);
    __syncthreads();

    for (int i4 = tid; i4 < 4096; i4 += 256) {
        int p = i4 >> 5, c = (i4 & 31) * 4;
        float4 o = *reinterpret_cast<float4*>(T + p * TSTR + c);
        o.x += __ldg(bias + c + 0);
        o.y += __ldg(bias + c + 1);
        o.z += __ldg(bias + c + 2);
        o.w += __ldg(bias + c + 3);
        reinterpret_cast<float4*>(g_hc + (size_t)(row0 + p) * DOUT)[i4 & 31] = o;
    }
}

// ---------------- 3: main GEMM (profiled) ----------------
__global__ __launch_bounds__(256, 2)
void main_mma_kernel(const float* __restrict__ feat, const float* __restrict__ logit,
                     const float* __restrict__ pts, const float* __restrict__ proj) {
    extern __shared__ __align__(16) char smem[];
    uint32_t smb = smem_u32(smem);
    int tid = threadIdx.x, wid = tid >> 5, lane = tid & 31;
    int wr = wid & 3, wc = wid >> 2;
    int row0 = blockIdx.x * 128;

    // g0: B + A chunk0
    issue_B(smb, tid, 0);
#pragma unroll
    for (int j = 0; j < 4; ++j) {
        int i = tid + 256 * j, p = i >> 3, u = i & 7;
        int r = row0 + p;
        const char* s = (r < NPTS) ? (const char*)feat + (size_t)r * 256 + u * 16 : (const char*)feat;
        cpa16(smb + p * ASTRB + u * 16, s, (r < NPTS) ? 16u : 0u);
    }
    cpa_commit();
    // g1: A chunk1
#pragma unroll
    for (int j = 0; j < 4; ++j) {
        int i = tid + 256 * j, p = i >> 3, u = i & 7;
        int r = row0 + p;
        const char* s = (r < NPTS) ? (const char*)feat + (size_t)r * 256 + 128 + u * 16 : (const char*)feat;
        cpa16(smb + ABUF + p * ASTRB + u * 16, s, (r < NPTS) ? 16u : 0u);
    }
    cpa_commit();

    float acc[64];
#pragma unroll
    for (int j = 0; j < 64; ++j) acc[j] = 0.f;
    const float sv[4] = {1.f, 1.f, 1.f, 1.f};

    cpa_wait<1>();
    __syncthreads();
    compute_chunk<false>(smem, smb, 0, 0, wr, wc, lane, sv, acc);
    __syncthreads();

    // chunk2 into buf0: logit (5 units) + pts (1 unit) async; proj + zero tail scalar
#pragma unroll
    for (int j = 0; j < 3; ++j) {
        int i = tid + 256 * j, p = i / 6, u = i - p * 6;
        int r = row0 + p;
        const char* s;
        if (r < NPTS) s = (u < 5) ? (const char*)logit + (size_t)r * 80 + u * 16
                                  : (const char*)pts + (size_t)r * 16;
        else s = (const char*)feat;
        cpa16(smb + p * ASTRB + u * 16, s, (r < NPTS) ? 16u : 0u);
    }
    cpa_commit();
    {
        float* A0 = reinterpret_cast<float*>(smem);
#pragma unroll
        for (int j = 0; j < 4; ++j) {
            int i = tid + 256 * j, p = i >> 3, kk = i & 7;
            int r = row0 + p;
            float v = (kk < 3 && r < NPTS) ? proj[(size_t)r * 3 + kk] : 0.f;
            A0[p * 40 + 24 + kk] = v;
        }
    }
    cpa_wait<1>();
    __syncthreads();
    compute_chunk<false>(smem, smb, ABUF, 1, wr, wc, lane, sv, acc);
    cpa_wait<0>();
    __syncthreads();
    compute_chunk<false>(smem, smb, 0, 2, wr, wc, lane, sv, acc);
    __syncthreads();

    float* T = reinterpret_cast<float*>(smem);
    frags_to_T(T, wid, lane, acc);
    __syncthreads();

    // cooperative hc add: cs loaded HERE (not mainloop-live); two batches of 8 LDG.128
    {
        int p0 = wid * 16;
        int rl = row0 + p0 + (lane & 15);
        int csl = (rl < NPTS) ? g_cs[rl] : 0;
#pragma unroll
        for (int half = 0; half < 2; ++half) {
            float4 hv[8];
#pragma unroll
            for (int it = 0; it < 8; ++it) {
                int cs = __shfl_sync(0xFFFFFFFFu, csl, half * 8 + it);
                hv[it] = reinterpret_cast<const float4*>(g_hc + (size_t)cs * DOUT)[lane];
            }
#pragma unroll
            for (int it = 0; it < 8; ++it) {
                int p = p0 + half * 8 + it;
                if (row0 + p < NPTS) {
                    float4* q = reinterpret_cast<float4*>(T + p * TSTR + 4 * lane);
                    float4 t = *q;
                    t.x += hv[it].x; t.y += hv[it].y; t.z += hv[it].z; t.w += hv[it].w;
                    *q = t;
                }
            }
        }
    }
    __syncthreads();

    // BN partials: 2 threads per column, shfl-reduced -> ONE atomic per column per block
    {
        int c = tid >> 1, pg = tid & 1;
        float s = 0.f, q = 0.f;
#pragma unroll 8
        for (int p = pg * 64; p < pg * 64 + 64; ++p) {
            float v = T[p * TSTR + c];
            s += v; q += v * v;
        }
        s += __shfl_down_sync(0xFFFFFFFFu, s, 1);
        q += __shfl_down_sync(0xFFFFFFFFu, q, 1);
        if (!pg) { atomicAdd(&g_bnsum[c], s); atomicAdd(&g_bnsq[c], q); }
    }

    // coalesced fp16 g_hh store
    {
        int rem = NPTS - row0;
        for (int i4 = tid; i4 < 4096; i4 += 256) {
            int p = i4 >> 5, c4 = i4 & 31;
            if (p < rem) {
                float4 o = *reinterpret_cast<float4*>(T + p * TSTR + c4 * 4);
                __half2 h0 = __floats2half2_rn(o.x, o.y);
                __half2 h1 = __floats2half2_rn(o.z, o.w);
                uint2 st;
                st.x = *reinterpret_cast<uint32_t*>(&h0);
                st.y = *reinterpret_cast<uint32_t*>(&h1);
                reinterpret_cast<uint2*>(g_hh + ((size_t)(row0 + p) << 7))[c4] = st;
            }
        }
    }
}

// ---------------- 4: BN finalize ----------------
__global__ void bn_finalize_kernel(const float* __restrict__ gamma,
                                   const float* __restrict__ beta) {
    int d = threadIdx.x;
    const float invN = 1.0f / (float)NPTS;
    float mu = g_bnsum[d] * invN;
    float var = g_bnsq[d] * invN - mu * mu;
    if (var < 0.f) var = 0.f;
    float sc = gamma[d] * rsqrtf(var + EPS);
    g_scale[d] = sc;
    g_shift[d] = beta[d] - mu * sc;
}

// ---------------- 5: map: wide (8 halfs / thread) ----------------
__global__ __launch_bounds__(256) void map_kernel(float* __restrict__ out) {
    __shared__ float sc[DOUT], sh[DOUT];
    int tid = threadIdx.x;
    if (tid < DOUT) { sc[tid] = g_scale[tid]; sh[tid] = g_shift[tid]; }
    __syncthreads();
    size_t gid = (size_t)blockIdx.x * 256 + tid;     // over uint4 (8 halfs)
    int d = ((int)(gid & 15)) * 8;
    uint4 raw = reinterpret_cast<const uint4*>(g_hh)[gid];
    float2 f0 = __half22float2(*reinterpret_cast<__half2*>(&raw.x));
    float2 f1 = __half22float2(*reinterpret_cast<__half2*>(&raw.y));
    float2 f2 = __half22float2(*reinterpret_cast<__half2*>(&raw.z));
    float2 f3 = __half22float2(*reinterpret_cast<__half2*>(&raw.w));
    float4 r0, r1;
    float v;
    v = f0.x * sc[d + 0] + sh[d + 0]; r0.x = (v >= 0.f) ? v : SLOPE * v;
    v = f0.y * sc[d + 1] + sh[d + 1]; r0.y = (v >= 0.f) ? v : SLOPE * v;
    v = f1.x * sc[d + 2] + sh[d + 2]; r0.z = (v >= 0.f) ? v : SLOPE * v;
    v = f1.y * sc[d + 3] + sh[d + 3]; r0.w = (v >= 0.f) ? v : SLOPE * v;
    v = f2.x * sc[d + 4] + sh[d + 4]; r1.x = (v >= 0.f) ? v : SLOPE * v;
    v = f2.y * sc[d + 5] + sh[d + 5]; r1.y = (v >= 0.f) ? v : SLOPE * v;
    v = f3.x * sc[d + 6] + sh[d + 6]; r1.z = (v >= 0.f) ? v : SLOPE * v;
    v = f3.y * sc[d + 7] + sh[d + 7]; r1.w = (v >= 0.f) ? v : SLOPE * v;
    reinterpret_cast<float4*>(out)[gid * 2 + 0] = r0;
    reinterpret_cast<float4*>(out)[gid * 2 + 1] = r1;
}

// ---------------- launch ----------------
extern "C" void kernel_launch(void* const* d_in, const int* in_sizes, int n_in,
                              void* d_out, int out_size) {
    const float* points = (const float*)d_in[0];
    const float* proj   = (const float*)d_in[1];
    const float* feat   = (const float*)d_in[2];
    const float* logits = (const float*)d_in[3];
    const int*   idx    = (const int*)d_in[4];
    const void*  mask   = d_in[5];
    const float* W      = (const float*)d_in[6];
    const float* bias   = (const float*)d_in[7];
    const float* gamma  = (const float*)d_in[8];
    const float* beta   = (const float*)d_in[9];
    float* out = (float*)d_out;

    cudaFuncSetAttribute(hc_mma_kernel, cudaFuncAttributeMaxDynamicSharedMemorySize, SMEM_BYTES);
    cudaFuncSetAttribute(main_mma_kernel, cudaFuncAttributeMaxDynamicSharedMemorySize, SMEM_BYTES);

    prep_all_kernel<<<7500, 256>>>((const unsigned char*)mask, W);
    scatter_kernel<<<(NPTS + 255) / 256, 256>>>(feat, logits, points, proj, idx, mask);
    hc_mma_kernel<<<2 * NCLU / 128, 256, SMEM_BYTES>>>(bias);
    // launch 3 (profiled): main GEMM
    main_mma_kernel<<<NTILES, 256, SMEM_BYTES>>>(feat, logits, points, proj);
    bn_finalize_kernel<<<1, DOUT>>>(gamma, beta);
    map_kernel<<<31250, 256>>>(out);   // 8M uint4 / 256
}

// round 14
// speedup vs baseline: 4.2439x; 1.0226x over previous
#include <cuda_runtime.h>
#include <cuda_bf16.h>
#include <cuda_fp16.h>
#include <cstdint>

#define NPTS 500000
#define NCLU 40000
#define KRAW 91
#define DOUT 128
#define NTILES 3907          // ceil(500000/128)
#define SUMS_STRIDE 96
#define EPS 1e-5f
#define SLOPE 0.1f

// ---- smem layout (bytes) ----
#define ASTRB 160            // A chunk row stride: 40 fp32
#define ABUF 20480           // one A chunk: 128 x 160B
#define BOFF 40960           // B region start
#define BSTRB 80             // B row stride: 40 bf16
#define BCHUNK 20480         // per-chunk: hi 10240 + lo 10240
#define SMEM_BYTES 102400    // 2 A bufs + 3 B chunks
#define TSTR 136             // fp32 T stride (544 B/row)

// ---------------- device scratch ----------------
__device__ __align__(16) float g_sums[2ull * NCLU * SUMS_STRIDE];
__device__ __align__(16) float g_hc[2ull * NCLU * DOUT];
__device__ __align__(16) __half g_hh[(size_t)NPTS * DOUT];
__device__ int g_cs[NPTS];
__device__ __align__(16) __nv_bfloat16 g_Wb2[2][3][2][128 * 40];
__device__ float g_bnsum[DOUT];
__device__ float g_bnsq[DOUT];
__device__ float g_scale[DOUT];
__device__ float g_shift[DOUT];
__device__ int   g_maskmode;

// ---------------- PTX helpers ----------------
__device__ __forceinline__ uint32_t smem_u32(const void* p) {
    uint32_t a;
    asm("{ .reg .u64 t; cvta.to.shared.u64 t, %1; cvt.u32.u64 %0, t; }" : "=r"(a) : "l"(p));
    return a;
}
__device__ __forceinline__ void cpa16(uint32_t dst, const void* src, uint32_t sz) {
    asm volatile("cp.async.cg.shared.global [%0], [%1], 16, %2;"
                 :: "r"(dst), "l"(src), "r"(sz) : "memory");
}
__device__ __forceinline__ void cpa_commit() {
    asm volatile("cp.async.commit_group;" ::: "memory");
}
template<int N> __device__ __forceinline__ void cpa_wait() {
    asm volatile("cp.async.wait_group %0;" :: "n"(N) : "memory");
}
__device__ __forceinline__ void ldsm4(uint32_t* r, uint32_t addr) {
    asm volatile("ldmatrix.sync.aligned.m8n8.x4.shared.b16 {%0,%1,%2,%3}, [%4];"
                 : "=r"(r[0]), "=r"(r[1]), "=r"(r[2]), "=r"(r[3]) : "r"(addr));
}
__device__ __forceinline__ void mma_bf16(float* d, const uint32_t* a, uint32_t b0, uint32_t b1) {
    asm volatile("mma.sync.aligned.m16n8k16.row.col.f32.bf16.bf16.f32 "
                 "{%0,%1,%2,%3}, {%4,%5,%6,%7}, {%8,%9}, {%0,%1,%2,%3};"
                 : "+f"(d[0]), "+f"(d[1]), "+f"(d[2]), "+f"(d[3])
                 : "r"(a[0]), "r"(a[1]), "r"(a[2]), "r"(a[3]), "r"(b0), "r"(b1));
}
__device__ __forceinline__ void red4(float* p, float a, float b, float c, float d) {
    asm volatile("red.global.add.v4.f32 [%0], {%1, %2, %3, %4};"
                 :: "l"(p), "f"(a), "f"(b), "f"(c), "f"(d) : "memory");
}
__device__ __forceinline__ void split_pair(float f0, float f1, uint32_t& hi, uint32_t& lo) {
    asm("cvt.rn.bf16x2.f32 %0, %1, %2;" : "=r"(hi) : "f"(f1), "f"(f0));
    float h0 = __uint_as_float(hi << 16);
    float h1 = __uint_as_float(hi & 0xFFFF0000u);
    asm("cvt.rn.bf16x2.f32 %0, %1, %2;" : "=r"(lo) : "f"(f1 - h1), "f"(f0 - h0));
}
__device__ __forceinline__ int get_fg(const void* m, int i, int mode) {
    if (mode == 0) return ((const unsigned char*)m)[i] != 0;
    if (mode == 1) return ((const float*)m)[i] != 0.0f;
    return ((const int*)m)[i] != 0;
}

// ---------------- 0: merged prep ----------------
__global__ void prep_all_kernel(const unsigned char* __restrict__ mask,
                                const float* __restrict__ W) {
    int tid = threadIdx.x;
    size_t gid = (size_t)blockIdx.x * 256 + tid;

    if (blockIdx.x == 0) {
        __shared__ int s1, s3;
        if (tid == 0) { s1 = 0; s3 = 0; }
        __syncthreads();
        int o1 = 0, o3 = 0;
        for (int i = tid; i < 16384; i += 256) { o1 |= mask[i * 4 + 1]; o3 |= mask[i * 4 + 3]; }
        atomicOr(&s1, o1); atomicOr(&s3, o3);
        __syncthreads();
        if (tid == 0) g_maskmode = s1 ? 0 : (s3 ? 1 : 2);
    }

    const size_t n4 = (size_t)2 * NCLU * SUMS_STRIDE / 4;
    float4 z = make_float4(0.f, 0.f, 0.f, 0.f);
    if (gid < n4) reinterpret_cast<float4*>(g_sums)[gid] = z;
    if (gid < 32) reinterpret_cast<float4*>(g_bnsum)[gid] = z;
    else if (gid < 64) reinterpret_cast<float4*>(g_bnsq)[gid - 32] = z;

    const int total = 2 * 3 * 2 * 128 * 40;
    if (gid < (size_t)total) {
        int t = (int)gid;
        int half = t / 30720;
        int rem = t - half * 30720;
        int c = rem / 10240;
        int rem2 = rem - c * 10240;
        int hl = rem2 / 5120;
        int r = rem2 - hl * 5120;
        int n = r / 40, kk = r - n * 40;
        int k = c * 32 + kk;
        float v = (kk < 32 && k < KRAW) ? W[(size_t)n * 182 + half * KRAW + k] : 0.f;
        if (hl == 0) {
            g_Wb2[half][c][0][r] = __float2bfloat16(v);
        } else {
            __nv_bfloat16 hi = __float2bfloat16(v);
            g_Wb2[half][c][1][r] = __float2bfloat16(v - __bfloat162float(hi));
        }
    }
}

// ---------------- 1: scatter (emits g_cs) ----------------
__global__ void scatter_kernel(const float* __restrict__ feat, const float* __restrict__ logit,
                               const float* __restrict__ pts, const float* __restrict__ proj,
                               const int* __restrict__ idx, const void* __restrict__ mask) {
    int i = blockIdx.x * blockDim.x + threadIdx.x;
    if (i >= NPTS) return;
    int mode = g_maskmode;
    int fg = get_fg(mask, i, mode);
    int cs = (fg ? 0 : NCLU) + idx[i];
    g_cs[i] = cs;

    float v[92];
    const float4* f4 = reinterpret_cast<const float4*>(feat + (size_t)i * 64);
#pragma unroll
    for (int j = 0; j < 16; ++j) {
        float4 t = f4[j];
        v[4*j] = t.x; v[4*j+1] = t.y; v[4*j+2] = t.z; v[4*j+3] = t.w;
    }
    const float4* l4 = reinterpret_cast<const float4*>(logit + (size_t)i * 20);
#pragma unroll
    for (int j = 0; j < 5; ++j) {
        float4 t = l4[j];
        v[64+4*j] = t.x; v[64+4*j+1] = t.y; v[64+4*j+2] = t.z; v[64+4*j+3] = t.w;
    }
    {
        float4 t = reinterpret_cast<const float4*>(pts + (size_t)i * 4)[0];
        v[84] = t.x; v[85] = t.y; v[86] = t.z; v[87] = t.w;
    }
    v[88] = proj[(size_t)i*3]; v[89] = proj[(size_t)i*3+1]; v[90] = proj[(size_t)i*3+2];
    v[91] = 1.0f;

    float* base = g_sums + (size_t)cs * SUMS_STRIDE;
#pragma unroll
    for (int j = 0; j < 23; ++j)
        red4(base + 4*j, v[4*j], v[4*j+1], v[4*j+2], v[4*j+3]);
}

// ---------------- shared mainloop pieces ----------------
template<bool SCALE>
__device__ __forceinline__ void compute_chunk(char* smem, uint32_t smb, int abuf_off, int bchunk,
                                              int wr, int wc, int lane,
                                              const float sv[4], float acc[64]) {
    char* abase = smem + abuf_off + (size_t)(wr * 32 + (lane >> 2)) * ASTRB + (lane & 3) * 8;
    uint32_t bbase = smb + BOFF + bchunk * BCHUNK
                   + (uint32_t)(wc * 64 + (lane & 7) + ((lane >> 4) & 1) * 8) * BSTRB
                   + ((lane >> 3) & 1) * 16;
#pragma unroll
    for (int ks = 0; ks < 2; ++ks) {
        uint32_t ah[2][4], al[2][4];
#pragma unroll
        for (int fr = 0; fr < 4; ++fr) {
            float2 u0 = *reinterpret_cast<float2*>(abase + fr * 8 * ASTRB + ks * 64);
            float2 u1 = *reinterpret_cast<float2*>(abase + fr * 8 * ASTRB + ks * 64 + 32);
            if (SCALE) {
                float s = sv[fr];
                u0.x *= s; u0.y *= s; u1.x *= s; u1.y *= s;
            }
            uint32_t hA, lA, hB, lB;
            split_pair(u0.x, u0.y, hA, lA);
            split_pair(u1.x, u1.y, hB, lB);
            int t = fr >> 1, rr = fr & 1;
            ah[t][rr] = hA; ah[t][2 + rr] = hB;
            al[t][rr] = lA; al[t][2 + rr] = lB;
        }
#pragma unroll
        for (int nb = 0; nb < 4; ++nb) {
            uint32_t bh[4], bl[4];
            uint32_t bo = (uint32_t)nb * 16 * BSTRB + ks * 32;
            ldsm4(bh, bbase + bo);
            ldsm4(bl, bbase + bo + 10240);
            float* c00 = acc + nb * 8;
            float* c01 = c00 + 4;
            float* c10 = acc + (4 + nb) * 8;
            float* c11 = c10 + 4;
            mma_bf16(c00, ah[0], bh[0], bh[1]); mma_bf16(c01, ah[0], bh[2], bh[3]);
            mma_bf16(c10, ah[1], bh[0], bh[1]); mma_bf16(c11, ah[1], bh[2], bh[3]);
            mma_bf16(c00, al[0], bh[0], bh[1]); mma_bf16(c01, al[0], bh[2], bh[3]);
            mma_bf16(c10, al[1], bh[0], bh[1]); mma_bf16(c11, al[1], bh[2], bh[3]);
            mma_bf16(c00, ah[0], bl[0], bl[1]); mma_bf16(c01, ah[0], bl[2], bl[3]);
            mma_bf16(c10, ah[1], bl[0], bl[1]); mma_bf16(c11, ah[1], bl[2], bl[3]);
        }
    }
}

__device__ __forceinline__ void frags_to_T(float* T, int wid, int lane, const float acc[64]) {
    int wr = wid & 3, wc = wid >> 2;
    int rbase = wr * 32 + (lane >> 2);
    int cb = wc * 64 + 2 * (lane & 3);
#pragma unroll
    for (int mrow = 0; mrow < 2; ++mrow) {
        int r0 = rbase + mrow * 16;
#pragma unroll
        for (int nb = 0; nb < 4; ++nb) {
#pragma unroll
            for (int t = 0; t < 2; ++t) {
                const float* a4 = acc + ((mrow * 4 + nb) * 2 + t) * 4;
                int c = cb + nb * 16 + t * 8;
                *reinterpret_cast<float2*>(T + r0 * TSTR + c) = make_float2(a4[0], a4[1]);
                *reinterpret_cast<float2*>(T + (r0 + 8) * TSTR + c) = make_float2(a4[2], a4[3]);
            }
        }
    }
}

__device__ __forceinline__ void issue_B(uint32_t smb, int tid, int half) {
    const char* src = (const char*)&g_Wb2[half][0][0][0];
#pragma unroll
    for (int j = 0; j < 15; ++j) {
        int i = tid + 256 * j;
        cpa16(smb + BOFF + i * 16, src + i * 16, 16);
    }
}

// ---------------- 2: hc = W2 @ mean + b ----------------
__global__ __launch_bounds__(256, 2)
void hc_mma_kernel(const float* __restrict__ bias) {
    extern __shared__ __align__(16) char smem[];
    __shared__ float s_inv[128];
    uint32_t smb = smem_u32(smem);
    int tid = threadIdx.x, wid = tid >> 5, lane = tid & 31;
    int wr = wid & 3, wc = wid >> 2;
    int row0 = blockIdx.x * 128;
    const char* sbase = (const char*)g_sums + (size_t)row0 * 384;

    issue_B(smb, tid, 1);
#pragma unroll
    for (int j = 0; j < 4; ++j) {
        int i = tid + 256 * j, p = i >> 3, u = i & 7;
        cpa16(smb + p * ASTRB + u * 16, sbase + (size_t)p * 384 + u * 16, 16);
    }
    cpa_commit();
#pragma unroll
    for (int j = 0; j < 4; ++j) {
        int i = tid + 256 * j, p = i >> 3, u = i & 7;
        cpa16(smb + ABUF + p * ASTRB + u * 16, sbase + (size_t)p * 384 + 128 + u * 16, 16);
    }
    cpa_commit();

    if (tid < 128) {
        float c = g_sums[(size_t)(row0 + tid) * SUMS_STRIDE + 91];
        s_inv[tid] = (c > 0.f) ? 1.0f / c : 0.0f;
    }

    float acc[64];
#pragma unroll
    for (int j = 0; j < 64; ++j) acc[j] = 0.f;

    cpa_wait<1>();
    __syncthreads();
    float sv[4];
#pragma unroll
    for (int fr = 0; fr < 4; ++fr) sv[fr] = s_inv[wr * 32 + (lane >> 2) + fr * 8];

    compute_chunk<true>(smem, smb, 0, 0, wr, wc, lane, sv, acc);
    __syncthreads();
#pragma unroll
    for (int j = 0; j < 4; ++j) {
        int i = tid + 256 * j, p = i >> 3, u = i & 7;
        cpa16(smb + p * ASTRB + u * 16, sbase + (size_t)p * 384 + 256 + u * 16, 16);
    }
    cpa_commit();
    cpa_wait<1>();
    __syncthreads();
    compute_chunk<true>(smem, smb, ABUF, 1, wr, wc, lane, sv, acc);
    cpa_wait<0>();
    __syncthreads();
    compute_chunk<true>(smem, smb, 0, 2, wr, wc, lane, sv, acc);
    __syncthreads();

    float* T = reinterpret_cast<float*>(smem);
    frags_to_T(T, wid, lane, acc);
    __syncthreads();

    for (int i4 = tid; i4 < 4096; i4 += 256) {
        int p = i4 >> 5, c = (i4 & 31) * 4;
        float4 o = *reinterpret_cast<float4*>(T + p * TSTR + c);
        o.x += __ldg(bias + c + 0);
        o.y += __ldg(bias + c + 1);
        o.z += __ldg(bias + c + 2);
        o.w += __ldg(bias + c + 3);
        reinterpret_cast<float4*>(g_hc + (size_t)(row0 + p) * DOUT)[i4 & 31] = o;
    }
}

// ---------------- 3: main GEMM (profiled) ----------------
__global__ __launch_bounds__(256, 2)
void main_mma_kernel(const float* __restrict__ feat, const float* __restrict__ logit,
                     const float* __restrict__ pts, const float* __restrict__ proj) {
    extern __shared__ __align__(16) char smem[];
    uint32_t smb = smem_u32(smem);
    int tid = threadIdx.x, wid = tid >> 5, lane = tid & 31;
    int wr = wid & 3, wc = wid >> 2;
    int row0 = blockIdx.x * 128;

    // g0: B + A chunk0
    issue_B(smb, tid, 0);
#pragma unroll
    for (int j = 0; j < 4; ++j) {
        int i = tid + 256 * j, p = i >> 3, u = i & 7;
        int r = row0 + p;
        const char* s = (r < NPTS) ? (const char*)feat + (size_t)r * 256 + u * 16 : (const char*)feat;
        cpa16(smb + p * ASTRB + u * 16, s, (r < NPTS) ? 16u : 0u);
    }
    cpa_commit();
    // g1: A chunk1
#pragma unroll
    for (int j = 0; j < 4; ++j) {
        int i = tid + 256 * j, p = i >> 3, u = i & 7;
        int r = row0 + p;
        const char* s = (r < NPTS) ? (const char*)feat + (size_t)r * 256 + 128 + u * 16 : (const char*)feat;
        cpa16(smb + ABUF + p * ASTRB + u * 16, s, (r < NPTS) ? 16u : 0u);
    }
    cpa_commit();

    float acc[64];
#pragma unroll
    for (int j = 0; j < 64; ++j) acc[j] = 0.f;
    const float sv[4] = {1.f, 1.f, 1.f, 1.f};

    cpa_wait<1>();
    __syncthreads();
    compute_chunk<false>(smem, smb, 0, 0, wr, wc, lane, sv, acc);
    __syncthreads();

    // chunk2 into buf0: logit (5 units) + pts (1 unit) async; proj + zero tail scalar
#pragma unroll
    for (int j = 0; j < 3; ++j) {
        int i = tid + 256 * j, p = i / 6, u = i - p * 6;
        int r = row0 + p;
        const char* s;
        if (r < NPTS) s = (u < 5) ? (const char*)logit + (size_t)r * 80 + u * 16
                                  : (const char*)pts + (size_t)r * 16;
        else s = (const char*)feat;
        cpa16(smb + p * ASTRB + u * 16, s, (r < NPTS) ? 16u : 0u);
    }
    cpa_commit();
    {
        float* A0 = reinterpret_cast<float*>(smem);
#pragma unroll
        for (int j = 0; j < 4; ++j) {
            int i = tid + 256 * j, p = i >> 3, kk = i & 7;
            int r = row0 + p;
            float v = (kk < 3 && r < NPTS) ? proj[(size_t)r * 3 + kk] : 0.f;
            A0[p * 40 + 24 + kk] = v;
        }
    }
    cpa_wait<1>();
    __syncthreads();
    compute_chunk<false>(smem, smb, ABUF, 1, wr, wc, lane, sv, acc);
    cpa_wait<0>();
    __syncthreads();
    compute_chunk<false>(smem, smb, 0, 2, wr, wc, lane, sv, acc);
    __syncthreads();

    float* T = reinterpret_cast<float*>(smem);
    frags_to_T(T, wid, lane, acc);
    __syncthreads();

    // cooperative hc add: cs loaded HERE (not mainloop-live); two batches of 8 LDG.128
    {
        int p0 = wid * 16;
        int rl = row0 + p0 + (lane & 15);
        int csl = (rl < NPTS) ? g_cs[rl] : 0;
#pragma unroll
        for (int half = 0; half < 2; ++half) {
            float4 hv[8];
#pragma unroll
            for (int it = 0; it < 8; ++it) {
                int cs = __shfl_sync(0xFFFFFFFFu, csl, half * 8 + it);
                hv[it] = reinterpret_cast<const float4*>(g_hc + (size_t)cs * DOUT)[lane];
            }
#pragma unroll
            for (int it = 0; it < 8; ++it) {
                int p = p0 + half * 8 + it;
                if (row0 + p < NPTS) {
                    float4* q = reinterpret_cast<float4*>(T + p * TSTR + 4 * lane);
                    float4 t = *q;
                    t.x += hv[it].x; t.y += hv[it].y; t.z += hv[it].z; t.w += hv[it].w;
                    *q = t;
                }
            }
        }
    }
    __syncthreads();

    // BN partials: 2 threads per column, shfl-reduced -> ONE atomic per column per block
    {
        int c = tid >> 1, pg = tid & 1;
        float s = 0.f, q = 0.f;
#pragma unroll 8
        for (int p = pg * 64; p < pg * 64 + 64; ++p) {
            float v = T[p * TSTR + c];
            s += v; q += v * v;
        }
        s += __shfl_down_sync(0xFFFFFFFFu, s, 1);
        q += __shfl_down_sync(0xFFFFFFFFu, q, 1);
        if (!pg) { atomicAdd(&g_bnsum[c], s); atomicAdd(&g_bnsq[c], q); }
    }

    // coalesced fp16 g_hh store
    {
        int rem = NPTS - row0;
        for (int i4 = tid; i4 < 4096; i4 += 256) {
            int p = i4 >> 5, c4 = i4 & 31;
            if (p < rem) {
                float4 o = *reinterpret_cast<float4*>(T + p * TSTR + c4 * 4);
                __half2 h0 = __floats2half2_rn(o.x, o.y);
                __half2 h1 = __floats2half2_rn(o.z, o.w);
                uint2 st;
                st.x = *reinterpret_cast<uint32_t*>(&h0);
                st.y = *reinterpret_cast<uint32_t*>(&h1);
                reinterpret_cast<uint2*>(g_hh + ((size_t)(row0 + p) << 7))[c4] = st;
            }
        }
    }
}

// ---------------- 4: BN finalize ----------------
__global__ void bn_finalize_kernel(const float* __restrict__ gamma,
                                   const float* __restrict__ beta) {
    int d = threadIdx.x;
    const float invN = 1.0f / (float)NPTS;
    float mu = g_bnsum[d] * invN;
    float var = g_bnsq[d] * invN - mu * mu;
    if (var < 0.f) var = 0.f;
    float sc = gamma[d] * rsqrtf(var + EPS);
    g_scale[d] = sc;
    g_shift[d] = beta[d] - mu * sc;
}

// ---------------- 5: map ----------------
__global__ __launch_bounds__(256) void map_kernel(float* __restrict__ out) {
    __shared__ float sc[DOUT], sh[DOUT];
    int tid = threadIdx.x;
    if (tid < DOUT) { sc[tid] = g_scale[tid]; sh[tid] = g_shift[tid]; }
    __syncthreads();
    size_t gid = (size_t)blockIdx.x * 256 + tid;
    int d = ((int)(gid & 31)) * 4;
    uint2 raw = reinterpret_cast<const uint2*>(g_hh)[gid];
    float2 f0 = __half22float2(*reinterpret_cast<__half2*>(&raw.x));
    float2 f1 = __half22float2(*reinterpret_cast<__half2*>(&raw.y));
    float4 r;
    float v;
    v = f0.x * sc[d + 0] + sh[d + 0]; r.x = (v >= 0.f) ? v : SLOPE * v;
    v = f0.y * sc[d + 1] + sh[d + 1]; r.y = (v >= 0.f) ? v : SLOPE * v;
    v = f1.x * sc[d + 2] + sh[d + 2]; r.z = (v >= 0.f) ? v : SLOPE * v;
    v = f1.y * sc[d + 3] + sh[d + 3]; r.w = (v >= 0.f) ? v : SLOPE * v;
    reinterpret_cast<float4*>(out)[gid] = r;
}

// ---------------- launch ----------------
extern "C" void kernel_launch(void* const* d_in, const int* in_sizes, int n_in,
                              void* d_out, int out_size) {
    const float* points = (const float*)d_in[0];
    const float* proj   = (const float*)d_in[1];
    const float* feat   = (const float*)d_in[2];
    const float* logits = (const float*)d_in[3];
    const int*   idx    = (const int*)d_in[4];
    const void*  mask   = d_in[5];
    const float* W      = (const float*)d_in[6];
    const float* bias   = (const float*)d_in[7];
    const float* gamma  = (const float*)d_in[8];
    const float* beta   = (const float*)d_in[9];
    float* out = (float*)d_out;

    cudaFuncSetAttribute(hc_mma_kernel, cudaFuncAttributeMaxDynamicSharedMemorySize, SMEM_BYTES);
    cudaFuncSetAttribute(main_mma_kernel, cudaFuncAttributeMaxDynamicSharedMemorySize, SMEM_BYTES);

    prep_all_kernel<<<7500, 256>>>((const unsigned char*)mask, W);
    scatter_kernel<<<(NPTS + 255) / 256, 256>>>(feat, logits, points, proj, idx, mask);
    hc_mma_kernel<<<2 * NCLU / 128, 256, SMEM_BYTES>>>(bias);
    // launch 3 (profiled): main GEMM
    main_mma_kernel<<<NTILES, 256, SMEM_BYTES>>>(feat, logits, points, proj);
    bn_finalize_kernel<<<1, DOUT>>>(gamma, beta);
    map_kernel<<<62500, 256>>>(out);   // 16M uint2 / 256
}

// round 15
// speedup vs baseline: 4.3514x; 1.0253x over previous
#include <cuda_runtime.h>
#include <cuda_bf16.h>
#include <cuda_fp16.h>
#include <cstdint>

#define NPTS 500000
#define NCLU 40000
#define KRAW 91
#define DOUT 128
#define NTILES 3907          // ceil(500000/128)
#define SUMS_STRIDE 96
#define EPS 1e-5f
#define SLOPE 0.1f

// ---- smem layout (bytes) ----
#define ASTRB 160            // A chunk row stride: 40 fp32
#define ABUF 20480           // one A chunk: 128 x 160B
#define BOFF 40960           // B region start
#define BSTRB 80             // B row stride: 40 f16
#define BCHUNK 20480         // per-chunk: hi 10240 + lo 10240
#define SMEM_BYTES 102400    // 2 A bufs + 3 B chunks
#define TSTR 136             // fp32 T stride (544 B/row)

// ---------------- device scratch ----------------
__device__ __align__(16) float g_sums[2ull * NCLU * SUMS_STRIDE];
__device__ __align__(16) float g_hc[2ull * NCLU * DOUT];
__device__ __align__(16) __half g_hh[(size_t)NPTS * DOUT];
__device__ int g_cs[NPTS];
__device__ __align__(16) __half g_Wf[2][3][2][128 * 40];   // [half][chunk][hi/lo][n*40] fp16
__device__ float g_bnsum[DOUT];
__device__ float g_bnsq[DOUT];
__device__ float g_scale[DOUT];
__device__ float g_shift[DOUT];
__device__ int   g_maskmode;

// ---------------- PTX helpers ----------------
__device__ __forceinline__ uint32_t smem_u32(const void* p) {
    uint32_t a;
    asm("{ .reg .u64 t; cvta.to.shared.u64 t, %1; cvt.u32.u64 %0, t; }" : "=r"(a) : "l"(p));
    return a;
}
__device__ __forceinline__ void cpa16(uint32_t dst, const void* src, uint32_t sz) {
    asm volatile("cp.async.cg.shared.global [%0], [%1], 16, %2;"
                 :: "r"(dst), "l"(src), "r"(sz) : "memory");
}
__device__ __forceinline__ void cpa_commit() {
    asm volatile("cp.async.commit_group;" ::: "memory");
}
template<int N> __device__ __forceinline__ void cpa_wait() {
    asm volatile("cp.async.wait_group %0;" :: "n"(N) : "memory");
}
__device__ __forceinline__ void ldsm4(uint32_t* r, uint32_t addr) {
    asm volatile("ldmatrix.sync.aligned.m8n8.x4.shared.b16 {%0,%1,%2,%3}, [%4];"
                 : "=r"(r[0]), "=r"(r[1]), "=r"(r[2]), "=r"(r[3]) : "r"(addr));
}
__device__ __forceinline__ void mma_f16(float* d, const uint32_t* a, uint32_t b0, uint32_t b1) {
    asm volatile("mma.sync.aligned.m16n8k16.row.col.f32.f16.f16.f32 "
                 "{%0,%1,%2,%3}, {%4,%5,%6,%7}, {%8,%9}, {%0,%1,%2,%3};"
                 : "+f"(d[0]), "+f"(d[1]), "+f"(d[2]), "+f"(d[3])
                 : "r"(a[0]), "r"(a[1]), "r"(a[2]), "r"(a[3]), "r"(b0), "r"(b1));
}
__device__ __forceinline__ void red4(float* p, float a, float b, float c, float d) {
    asm volatile("red.global.add.v4.f32 [%0], {%1, %2, %3, %4};"
                 :: "l"(p), "f"(a), "f"(b), "f"(c), "f"(d) : "memory");
}
// pack two fp32 (f0 = lower k) into f16x2 (lo = f0, hi = f1)
__device__ __forceinline__ uint32_t pack_f16x2(float f0, float f1) {
    uint32_t r;
    asm("cvt.rn.f16x2.f32 %0, %1, %2;" : "=r"(r) : "f"(f1), "f"(f0));
    return r;
}
__device__ __forceinline__ int get_fg(const void* m, int i, int mode) {
    if (mode == 0) return ((const unsigned char*)m)[i] != 0;
    if (mode == 1) return ((const float*)m)[i] != 0.0f;
    return ((const int*)m)[i] != 0;
}

// ---------------- 0: merged prep ----------------
__global__ void prep_all_kernel(const unsigned char* __restrict__ mask,
                                const float* __restrict__ W) {
    int tid = threadIdx.x;
    size_t gid = (size_t)blockIdx.x * 256 + tid;

    if (blockIdx.x == 0) {
        __shared__ int s1, s3;
        if (tid == 0) { s1 = 0; s3 = 0; }
        __syncthreads();
        int o1 = 0, o3 = 0;
        for (int i = tid; i < 16384; i += 256) { o1 |= mask[i * 4 + 1]; o3 |= mask[i * 4 + 3]; }
        atomicOr(&s1, o1); atomicOr(&s3, o3);
        __syncthreads();
        if (tid == 0) g_maskmode = s1 ? 0 : (s3 ? 1 : 2);
    }

    const size_t n4 = (size_t)2 * NCLU * SUMS_STRIDE / 4;
    float4 z = make_float4(0.f, 0.f, 0.f, 0.f);
    if (gid < n4) reinterpret_cast<float4*>(g_sums)[gid] = z;
    if (gid < 32) reinterpret_cast<float4*>(g_bnsum)[gid] = z;
    else if (gid < 64) reinterpret_cast<float4*>(g_bnsq)[gid - 32] = z;

    // W split: fp16 hi + fp16 residual lo
    const int total = 2 * 3 * 2 * 128 * 40;
    if (gid < (size_t)total) {
        int t = (int)gid;
        int half = t / 30720;
        int rem = t - half * 30720;
        int c = rem / 10240;
        int rem2 = rem - c * 10240;
        int hl = rem2 / 5120;
        int r = rem2 - hl * 5120;
        int n = r / 40, kk = r - n * 40;
        int k = c * 32 + kk;
        float v = (kk < 32 && k < KRAW) ? W[(size_t)n * 182 + half * KRAW + k] : 0.f;
        if (hl == 0) {
            g_Wf[half][c][0][r] = __float2half_rn(v);
        } else {
            __half hi = __float2half_rn(v);
            g_Wf[half][c][1][r] = __float2half_rn(v - __half2float(hi));
        }
    }
}

// ---------------- 1: scatter (emits g_cs) ----------------
__global__ void scatter_kernel(const float* __restrict__ feat, const float* __restrict__ logit,
                               const float* __restrict__ pts, const float* __restrict__ proj,
                               const int* __restrict__ idx, const void* __restrict__ mask) {
    int i = blockIdx.x * blockDim.x + threadIdx.x;
    if (i >= NPTS) return;
    int mode = g_maskmode;
    int fg = get_fg(mask, i, mode);
    int cs = (fg ? 0 : NCLU) + idx[i];
    g_cs[i] = cs;

    float v[92];
    const float4* f4 = reinterpret_cast<const float4*>(feat + (size_t)i * 64);
#pragma unroll
    for (int j = 0; j < 16; ++j) {
        float4 t = f4[j];
        v[4*j] = t.x; v[4*j+1] = t.y; v[4*j+2] = t.z; v[4*j+3] = t.w;
    }
    const float4* l4 = reinterpret_cast<const float4*>(logit + (size_t)i * 20);
#pragma unroll
    for (int j = 0; j < 5; ++j) {
        float4 t = l4[j];
        v[64+4*j] = t.x; v[64+4*j+1] = t.y; v[64+4*j+2] = t.z; v[64+4*j+3] = t.w;
    }
    {
        float4 t = reinterpret_cast<const float4*>(pts + (size_t)i * 4)[0];
        v[84] = t.x; v[85] = t.y; v[86] = t.z; v[87] = t.w;
    }
    v[88] = proj[(size_t)i*3]; v[89] = proj[(size_t)i*3+1]; v[90] = proj[(size_t)i*3+2];
    v[91] = 1.0f;

    float* base = g_sums + (size_t)cs * SUMS_STRIDE;
#pragma unroll
    for (int j = 0; j < 23; ++j)
        red4(base + 4*j, v[4*j], v[4*j+1], v[4*j+2], v[4*j+3]);
}

// ---------------- shared mainloop pieces ----------------
// A single-term fp16; B = W_hi + W_lo (fp16 pair). 8 MMAs per nb.
template<bool SCALE>
__device__ __forceinline__ void compute_chunk(char* smem, uint32_t smb, int abuf_off, int bchunk,
                                              int wr, int wc, int lane,
                                              const float sv[4], float acc[64]) {
    char* abase = smem + abuf_off + (size_t)(wr * 32 + (lane >> 2)) * ASTRB + (lane & 3) * 8;
    uint32_t bbase = smb + BOFF + bchunk * BCHUNK
                   + (uint32_t)(wc * 64 + (lane & 7) + ((lane >> 4) & 1) * 8) * BSTRB
                   + ((lane >> 3) & 1) * 16;
#pragma unroll
    for (int ks = 0; ks < 2; ++ks) {
        uint32_t ah[2][4];
#pragma unroll
        for (int fr = 0; fr < 4; ++fr) {
            float2 u0 = *reinterpret_cast<float2*>(abase + fr * 8 * ASTRB + ks * 64);
            float2 u1 = *reinterpret_cast<float2*>(abase + fr * 8 * ASTRB + ks * 64 + 32);
            if (SCALE) {
                float s = sv[fr];
                u0.x *= s; u0.y *= s; u1.x *= s; u1.y *= s;
            }
            int t = fr >> 1, rr = fr & 1;
            ah[t][rr] = pack_f16x2(u0.x, u0.y);
            ah[t][2 + rr] = pack_f16x2(u1.x, u1.y);
        }
#pragma unroll
        for (int nb = 0; nb < 4; ++nb) {
            uint32_t bh[4], bl[4];
            uint32_t bo = (uint32_t)nb * 16 * BSTRB + ks * 32;
            ldsm4(bh, bbase + bo);
            ldsm4(bl, bbase + bo + 10240);
            float* c00 = acc + nb * 8;
            float* c01 = c00 + 4;
            float* c10 = acc + (4 + nb) * 8;
            float* c11 = c10 + 4;
            mma_f16(c00, ah[0], bh[0], bh[1]); mma_f16(c01, ah[0], bh[2], bh[3]);
            mma_f16(c10, ah[1], bh[0], bh[1]); mma_f16(c11, ah[1], bh[2], bh[3]);
            mma_f16(c00, ah[0], bl[0], bl[1]); mma_f16(c01, ah[0], bl[2], bl[3]);
            mma_f16(c10, ah[1], bl[0], bl[1]); mma_f16(c11, ah[1], bl[2], bl[3]);
        }
    }
}

__device__ __forceinline__ void frags_to_T(float* T, int wid, int lane, const float acc[64]) {
    int wr = wid & 3, wc = wid >> 2;
    int rbase = wr * 32 + (lane >> 2);
    int cb = wc * 64 + 2 * (lane & 3);
#pragma unroll
    for (int mrow = 0; mrow < 2; ++mrow) {
        int r0 = rbase + mrow * 16;
#pragma unroll
        for (int nb = 0; nb < 4; ++nb) {
#pragma unroll
            for (int t = 0; t < 2; ++t) {
                const float* a4 = acc + ((mrow * 4 + nb) * 2 + t) * 4;
                int c = cb + nb * 16 + t * 8;
                *reinterpret_cast<float2*>(T + r0 * TSTR + c) = make_float2(a4[0], a4[1]);
                *reinterpret_cast<float2*>(T + (r0 + 8) * TSTR + c) = make_float2(a4[2], a4[3]);
            }
        }
    }
}

__device__ __forceinline__ void issue_B(uint32_t smb, int tid, int half) {
    const char* src = (const char*)&g_Wf[half][0][0][0];
#pragma unroll
    for (int j = 0; j < 15; ++j) {
        int i = tid + 256 * j;
        cpa16(smb + BOFF + i * 16, src + i * 16, 16);
    }
}

// ---------------- 2: hc = W2 @ mean + b ----------------
__global__ __launch_bounds__(256, 2)
void hc_mma_kernel(const float* __restrict__ bias) {
    extern __shared__ __align__(16) char smem[];
    __shared__ float s_inv[128];
    uint32_t smb = smem_u32(smem);
    int tid = threadIdx.x, wid = tid >> 5, lane = tid & 31;
    int wr = wid & 3, wc = wid >> 2;
    int row0 = blockIdx.x * 128;
    const char* sbase = (const char*)g_sums + (size_t)row0 * 384;

    issue_B(smb, tid, 1);
#pragma unroll
    for (int j = 0; j < 4; ++j) {
        int i = tid + 256 * j, p = i >> 3, u = i & 7;
        cpa16(smb + p * ASTRB + u * 16, sbase + (size_t)p * 384 + u * 16, 16);
    }
    cpa_commit();
#pragma unroll
    for (int j = 0; j < 4; ++j) {
        int i = tid + 256 * j, p = i >> 3, u = i & 7;
        cpa16(smb + ABUF + p * ASTRB + u * 16, sbase + (size_t)p * 384 + 128 + u * 16, 16);
    }
    cpa_commit();

    if (tid < 128) {
        float c = g_sums[(size_t)(row0 + tid) * SUMS_STRIDE + 91];
        s_inv[tid] = (c > 0.f) ? 1.0f / c : 0.0f;
    }

    float acc[64];
#pragma unroll
    for (int j = 0; j < 64; ++j) acc[j] = 0.f;

    cpa_wait<1>();
    __syncthreads();
    float sv[4];
#pragma unroll
    for (int fr = 0; fr < 4; ++fr) sv[fr] = s_inv[wr * 32 + (lane >> 2) + fr * 8];

    compute_chunk<true>(smem, smb, 0, 0, wr, wc, lane, sv, acc);
    __syncthreads();
#pragma unroll
    for (int j = 0; j < 4; ++j) {
        int i = tid + 256 * j, p = i >> 3, u = i & 7;
        cpa16(smb + p * ASTRB + u * 16, sbase + (size_t)p * 384 + 256 + u * 16, 16);
    }
    cpa_commit();
    cpa_wait<1>();
    __syncthreads();
    compute_chunk<true>(smem, smb, ABUF, 1, wr, wc, lane, sv, acc);
    cpa_wait<0>();
    __syncthreads();
    compute_chunk<true>(smem, smb, 0, 2, wr, wc, lane, sv, acc);
    __syncthreads();

    float* T = reinterpret_cast<float*>(smem);
    frags_to_T(T, wid, lane, acc);
    __syncthreads();

    for (int i4 = tid; i4 < 4096; i4 += 256) {
        int p = i4 >> 5, c = (i4 & 31) * 4;
        float4 o = *reinterpret_cast<float4*>(T + p * TSTR + c);
        o.x += __ldg(bias + c + 0);
        o.y += __ldg(bias + c + 1);
        o.z += __ldg(bias + c + 2);
        o.w += __ldg(bias + c + 3);
        reinterpret_cast<float4*>(g_hc + (size_t)(row0 + p) * DOUT)[i4 & 31] = o;
    }
}

// ---------------- 3: main GEMM (profiled) ----------------
__global__ __launch_bounds__(256, 2)
void main_mma_kernel(const float* __restrict__ feat, const float* __restrict__ logit,
                     const float* __restrict__ pts, const float* __restrict__ proj) {
    extern __shared__ __align__(16) char smem[];
    uint32_t smb = smem_u32(smem);
    int tid = threadIdx.x, wid = tid >> 5, lane = tid & 31;
    int wr = wid & 3, wc = wid >> 2;
    int row0 = blockIdx.x * 128;

    // g0: B + A chunk0
    issue_B(smb, tid, 0);
#pragma unroll
    for (int j = 0; j < 4; ++j) {
        int i = tid + 256 * j, p = i >> 3, u = i & 7;
        int r = row0 + p;
        const char* s = (r < NPTS) ? (const char*)feat + (size_t)r * 256 + u * 16 : (const char*)feat;
        cpa16(smb + p * ASTRB + u * 16, s, (r < NPTS) ? 16u : 0u);
    }
    cpa_commit();
    // g1: A chunk1
#pragma unroll
    for (int j = 0; j < 4; ++j) {
        int i = tid + 256 * j, p = i >> 3, u = i & 7;
        int r = row0 + p;
        const char* s = (r < NPTS) ? (const char*)feat + (size_t)r * 256 + 128 + u * 16 : (const char*)feat;
        cpa16(smb + ABUF + p * ASTRB + u * 16, s, (r < NPTS) ? 16u : 0u);
    }
    cpa_commit();

    float acc[64];
#pragma unroll
    for (int j = 0; j < 64; ++j) acc[j] = 0.f;
    const float sv[4] = {1.f, 1.f, 1.f, 1.f};

    cpa_wait<1>();
    __syncthreads();
    compute_chunk<false>(smem, smb, 0, 0, wr, wc, lane, sv, acc);
    __syncthreads();

    // chunk2 into buf0: logit (5 units) + pts (1 unit) async; proj + zero tail scalar
#pragma unroll
    for (int j = 0; j < 3; ++j) {
        int i = tid + 256 * j, p = i / 6, u = i - p * 6;
        int r = row0 + p;
        const char* s;
        if (r < NPTS) s = (u < 5) ? (const char*)logit + (size_t)r * 80 + u * 16
                                  : (const char*)pts + (size_t)r * 16;
        else s = (const char*)feat;
        cpa16(smb + p * ASTRB + u * 16, s, (r < NPTS) ? 16u : 0u);
    }
    cpa_commit();
    {
        float* A0 = reinterpret_cast<float*>(smem);
#pragma unroll
        for (int j = 0; j < 4; ++j) {
            int i = tid + 256 * j, p = i >> 3, kk = i & 7;
            int r = row0 + p;
            float v = (kk < 3 && r < NPTS) ? proj[(size_t)r * 3 + kk] : 0.f;
            A0[p * 40 + 24 + kk] = v;
        }
    }
    cpa_wait<1>();
    __syncthreads();
    compute_chunk<false>(smem, smb, ABUF, 1, wr, wc, lane, sv, acc);
    cpa_wait<0>();
    __syncthreads();
    compute_chunk<false>(smem, smb, 0, 2, wr, wc, lane, sv, acc);
    __syncthreads();

    float* T = reinterpret_cast<float*>(smem);
    frags_to_T(T, wid, lane, acc);
    __syncthreads();

    // cooperative hc add: cs loaded HERE (not mainloop-live); two batches of 8 LDG.128
    {
        int p0 = wid * 16;
        int rl = row0 + p0 + (lane & 15);
        int csl = (rl < NPTS) ? g_cs[rl] : 0;
#pragma unroll
        for (int half = 0; half < 2; ++half) {
            float4 hv[8];
#pragma unroll
            for (int it = 0; it < 8; ++it) {
                int cs = __shfl_sync(0xFFFFFFFFu, csl, half * 8 + it);
                hv[it] = reinterpret_cast<const float4*>(g_hc + (size_t)cs * DOUT)[lane];
            }
#pragma unroll
            for (int it = 0; it < 8; ++it) {
                int p = p0 + half * 8 + it;
                if (row0 + p < NPTS) {
                    float4* q = reinterpret_cast<float4*>(T + p * TSTR + 4 * lane);
                    float4 t = *q;
                    t.x += hv[it].x; t.y += hv[it].y; t.z += hv[it].z; t.w += hv[it].w;
                    *q = t;
                }
            }
        }
    }
    __syncthreads();

    // BN partials: 2 threads per column, shfl-reduced -> ONE atomic per column per block
    {
        int c = tid >> 1, pg = tid & 1;
        float s = 0.f, q = 0.f;
#pragma unroll 8
        for (int p = pg * 64; p < pg * 64 + 64; ++p) {
            float v = T[p * TSTR + c];
            s += v; q += v * v;
        }
        s += __shfl_down_sync(0xFFFFFFFFu, s, 1);
        q += __shfl_down_sync(0xFFFFFFFFu, q, 1);
        if (!pg) { atomicAdd(&g_bnsum[c], s); atomicAdd(&g_bnsq[c], q); }
    }

    // coalesced fp16 g_hh store
    {
        int rem = NPTS - row0;
        for (int i4 = tid; i4 < 4096; i4 += 256) {
            int p = i4 >> 5, c4 = i4 & 31;
            if (p < rem) {
                float4 o = *reinterpret_cast<float4*>(T + p * TSTR + c4 * 4);
                __half2 h0 = __floats2half2_rn(o.x, o.y);
                __half2 h1 = __floats2half2_rn(o.z, o.w);
                uint2 st;
                st.x = *reinterpret_cast<uint32_t*>(&h0);
                st.y = *reinterpret_cast<uint32_t*>(&h1);
                reinterpret_cast<uint2*>(g_hh + ((size_t)(row0 + p) << 7))[c4] = st;
            }
        }
    }
}

// ---------------- 4: BN finalize ----------------
__global__ void bn_finalize_kernel(const float* __restrict__ gamma,
                                   const float* __restrict__ beta) {
    int d = threadIdx.x;
    const float invN = 1.0f / (float)NPTS;
    float mu = g_bnsum[d] * invN;
    float var = g_bnsq[d] * invN - mu * mu;
    if (var < 0.f) var = 0.f;
    float sc = gamma[d] * rsqrtf(var + EPS);
    g_scale[d] = sc;
    g_shift[d] = beta[d] - mu * sc;
}

// ---------------- 5: map ----------------
__global__ __launch_bounds__(256) void map_kernel(float* __restrict__ out) {
    __shared__ float sc[DOUT], sh[DOUT];
    int tid = threadIdx.x;
    if (tid < DOUT) { sc[tid] = g_scale[tid]; sh[tid] = g_shift[tid]; }
    __syncthreads();
    size_t gid = (size_t)blockIdx.x * 256 + tid;
    int d = ((int)(gid & 31)) * 4;
    uint2 raw = reinterpret_cast<const uint2*>(g_hh)[gid];
    float2 f0 = __half22float2(*reinterpret_cast<__half2*>(&raw.x));
    float2 f1 = __half22float2(*reinterpret_cast<__half2*>(&raw.y));
    float4 r;
    float v;
    v = f0.x * sc[d + 0] + sh[d + 0]; r.x = (v >= 0.f) ? v : SLOPE * v;
    v = f0.y * sc[d + 1] + sh[d + 1]; r.y = (v >= 0.f) ? v : SLOPE * v;
    v = f1.x * sc[d + 2] + sh[d + 2]; r.z = (v >= 0.f) ? v : SLOPE * v;
    v = f1.y * sc[d + 3] + sh[d + 3]; r.w = (v >= 0.f) ? v : SLOPE * v;
    reinterpret_cast<float4*>(out)[gid] = r;
}

// ---------------- launch ----------------
extern "C" void kernel_launch(void* const* d_in, const int* in_sizes, int n_in,
                              void* d_out, int out_size) {
    const float* points = (const float*)d_in[0];
    const float* proj   = (const float*)d_in[1];
    const float* feat   = (const float*)d_in[2];
    const float* logits = (const float*)d_in[3];
    const int*   idx    = (const int*)d_in[4];
    const void*  mask   = d_in[5];
    const float* W      = (const float*)d_in[6];
    const float* bias   = (const float*)d_in[7];
    const float* gamma  = (const float*)d_in[8];
    const float* beta   = (const float*)d_in[9];
    float* out = (float*)d_out;

    cudaFuncSetAttribute(hc_mma_kernel, cudaFuncAttributeMaxDynamicSharedMemorySize, SMEM_BYTES);
    cudaFuncSetAttribute(main_mma_kernel, cudaFuncAttributeMaxDynamicSharedMemorySize, SMEM_BYTES);

    prep_all_kernel<<<7500, 256>>>((const unsigned char*)mask, W);
    scatter_kernel<<<(NPTS + 255) / 256, 256>>>(feat, logits, points, proj, idx, mask);
    hc_mma_kernel<<<2 * NCLU / 128, 256, SMEM_BYTES>>>(bias);
    // launch 3 (profiled): main GEMM
    main_mma_kernel<<<NTILES, 256, SMEM_BYTES>>>(feat, logits, points, proj);
    bn_finalize_kernel<<<1, DOUT>>>(gamma, beta);
    map_kernel<<<62500, 256>>>(out);   // 16M uint2 / 256
}

// round 16
// speedup vs baseline: 4.7544x; 1.0926x over previous
#include <cuda_runtime.h>
#include <cuda_bf16.h>
#include <cuda_fp16.h>
#include <cstdint>

#define NPTS 500000
#define NCLU 40000
#define KRAW 91
#define DOUT 128
#define NTILES 3907          // ceil(500000/128)
#define SUMS_STRIDE 96
#define EPS 1e-5f
#define SLOPE 0.1f

// ---- smem layout (bytes) ----
#define ASTRB 160            // A chunk row stride: 40 fp32
#define ABUF 20480           // one A chunk: 128 x 160B
#define BOFF 40960           // B region start
#define BSTRB 80             // B row stride: 40 f16
#define BCHUNK 10240         // per-chunk: hi only (128 x 80B)
#define SMEM_BYTES 71680     // 2 A bufs + 3 B chunks
#define TSTR 136             // fp32 T stride (544 B/row)

// ---------------- device scratch ----------------
__device__ __align__(16) float g_sums[2ull * NCLU * SUMS_STRIDE];
__device__ __align__(16) float g_hc[2ull * NCLU * DOUT];
__device__ __align__(16) __half g_hh[(size_t)NPTS * DOUT];
__device__ int g_cs[NPTS];
__device__ __align__(16) __half g_Wf[2][3][128 * 40];   // [half][chunk][n*40] fp16
__device__ float g_bnsum[DOUT];
__device__ float g_bnsq[DOUT];
__device__ float g_scale[DOUT];
__device__ float g_shift[DOUT];
__device__ int   g_maskmode;

// ---------------- PTX helpers ----------------
__device__ __forceinline__ uint32_t smem_u32(const void* p) {
    uint32_t a;
    asm("{ .reg .u64 t; cvta.to.shared.u64 t, %1; cvt.u32.u64 %0, t; }" : "=r"(a) : "l"(p));
    return a;
}
__device__ __forceinline__ void cpa16(uint32_t dst, const void* src, uint32_t sz) {
    asm volatile("cp.async.cg.shared.global [%0], [%1], 16, %2;"
                 :: "r"(dst), "l"(src), "r"(sz) : "memory");
}
__device__ __forceinline__ void cpa_commit() {
    asm volatile("cp.async.commit_group;" ::: "memory");
}
template<int N> __device__ __forceinline__ void cpa_wait() {
    asm volatile("cp.async.wait_group %0;" :: "n"(N) : "memory");
}
__device__ __forceinline__ void ldsm4(uint32_t* r, uint32_t addr) {
    asm volatile("ldmatrix.sync.aligned.m8n8.x4.shared.b16 {%0,%1,%2,%3}, [%4];"
                 : "=r"(r[0]), "=r"(r[1]), "=r"(r[2]), "=r"(r[3]) : "r"(addr));
}
__device__ __forceinline__ void mma_f16(float* d, const uint32_t* a, uint32_t b0, uint32_t b1) {
    asm volatile("mma.sync.aligned.m16n8k16.row.col.f32.f16.f16.f32 "
                 "{%0,%1,%2,%3}, {%4,%5,%6,%7}, {%8,%9}, {%0,%1,%2,%3};"
                 : "+f"(d[0]), "+f"(d[1]), "+f"(d[2]), "+f"(d[3])
                 : "r"(a[0]), "r"(a[1]), "r"(a[2]), "r"(a[3]), "r"(b0), "r"(b1));
}
__device__ __forceinline__ void red4(float* p, float a, float b, float c, float d) {
    asm volatile("red.global.add.v4.f32 [%0], {%1, %2, %3, %4};"
                 :: "l"(p), "f"(a), "f"(b), "f"(c), "f"(d) : "memory");
}
// pack two fp32 (f0 = lower k) into f16x2 (lo = f0, hi = f1)
__device__ __forceinline__ uint32_t pack_f16x2(float f0, float f1) {
    uint32_t r;
    asm("cvt.rn.f16x2.f32 %0, %1, %2;" : "=r"(r) : "f"(f1), "f"(f0));
    return r;
}
__device__ __forceinline__ int get_fg(const void* m, int i, int mode) {
    if (mode == 0) return ((const unsigned char*)m)[i] != 0;
    if (mode == 1) return ((const float*)m)[i] != 0.0f;
    return ((const int*)m)[i] != 0;
}

// ---------------- 0: merged prep ----------------
__global__ void prep_all_kernel(const unsigned char* __restrict__ mask,
                                const float* __restrict__ W) {
    int tid = threadIdx.x;
    size_t gid = (size_t)blockIdx.x * 256 + tid;

    if (blockIdx.x == 0) {
        __shared__ int s1, s3;
        if (tid == 0) { s1 = 0; s3 = 0; }
        __syncthreads();
        int o1 = 0, o3 = 0;
        for (int i = tid; i < 16384; i += 256) { o1 |= mask[i * 4 + 1]; o3 |= mask[i * 4 + 3]; }
        atomicOr(&s1, o1); atomicOr(&s3, o3);
        __syncthreads();
        if (tid == 0) g_maskmode = s1 ? 0 : (s3 ? 1 : 2);
    }

    const size_t n4 = (size_t)2 * NCLU * SUMS_STRIDE / 4;
    float4 z = make_float4(0.f, 0.f, 0.f, 0.f);
    if (gid < n4) reinterpret_cast<float4*>(g_sums)[gid] = z;
    if (gid < 32) reinterpret_cast<float4*>(g_bnsum)[gid] = z;
    else if (gid < 64) reinterpret_cast<float4*>(g_bnsq)[gid - 32] = z;

    // W -> fp16, per-chunk layout [half][chunk][n][40]
    const int total = 2 * 3 * 128 * 40;   // 30720
    if (gid < (size_t)total) {
        int t = (int)gid;
        int half = t / 15360;
        int rem = t - half * 15360;
        int c = rem / 5120;
        int r = rem - c * 5120;
        int n = r / 40, kk = r - n * 40;
        int k = c * 32 + kk;
        float v = (kk < 32 && k < KRAW) ? W[(size_t)n * 182 + half * KRAW + k] : 0.f;
        g_Wf[half][c][r] = __float2half_rn(v);
    }
}

// ---------------- 1: scatter (emits g_cs) ----------------
__global__ void scatter_kernel(const float* __restrict__ feat, const float* __restrict__ logit,
                               const float* __restrict__ pts, const float* __restrict__ proj,
                               const int* __restrict__ idx, const void* __restrict__ mask) {
    int i = blockIdx.x * blockDim.x + threadIdx.x;
    if (i >= NPTS) return;
    int mode = g_maskmode;
    int fg = get_fg(mask, i, mode);
    int cs = (fg ? 0 : NCLU) + idx[i];
    g_cs[i] = cs;

    float v[92];
    const float4* f4 = reinterpret_cast<const float4*>(feat + (size_t)i * 64);
#pragma unroll
    for (int j = 0; j < 16; ++j) {
        float4 t = f4[j];
        v[4*j] = t.x; v[4*j+1] = t.y; v[4*j+2] = t.z; v[4*j+3] = t.w;
    }
    const float4* l4 = reinterpret_cast<const float4*>(logit + (size_t)i * 20);
#pragma unroll
    for (int j = 0; j < 5; ++j) {
        float4 t = l4[j];
        v[64+4*j] = t.x; v[64+4*j+1] = t.y; v[64+4*j+2] = t.z; v[64+4*j+3] = t.w;
    }
    {
        float4 t = reinterpret_cast<const float4*>(pts + (size_t)i * 4)[0];
        v[84] = t.x; v[85] = t.y; v[86] = t.z; v[87] = t.w;
    }
    v[88] = proj[(size_t)i*3]; v[89] = proj[(size_t)i*3+1]; v[90] = proj[(size_t)i*3+2];
    v[91] = 1.0f;

    float* base = g_sums + (size_t)cs * SUMS_STRIDE;
#pragma unroll
    for (int j = 0; j < 23; ++j)
        red4(base + 4*j, v[4*j], v[4*j+1], v[4*j+2], v[4*j+3]);
}

// ---------------- shared mainloop pieces ----------------
// A fp16 packed from fp32; B single fp16 image. 4 MMAs per nb.
template<bool SCALE>
__device__ __forceinline__ void compute_chunk(char* smem, uint32_t smb, int abuf_off, int bchunk,
                                              int wr, int wc, int lane,
                                              const float sv[4], float acc[64]) {
    char* abase = smem + abuf_off + (size_t)(wr * 32 + (lane >> 2)) * ASTRB + (lane & 3) * 8;
    uint32_t bbase = smb + BOFF + bchunk * BCHUNK
                   + (uint32_t)(wc * 64 + (lane & 7) + ((lane >> 4) & 1) * 8) * BSTRB
                   + ((lane >> 3) & 1) * 16;
#pragma unroll
    for (int ks = 0; ks < 2; ++ks) {
        uint32_t ah[2][4];
#pragma unroll
        for (int fr = 0; fr < 4; ++fr) {
            float2 u0 = *reinterpret_cast<float2*>(abase + fr * 8 * ASTRB + ks * 64);
            float2 u1 = *reinterpret_cast<float2*>(abase + fr * 8 * ASTRB + ks * 64 + 32);
            if (SCALE) {
                float s = sv[fr];
                u0.x *= s; u0.y *= s; u1.x *= s; u1.y *= s;
            }
            int t = fr >> 1, rr = fr & 1;
            ah[t][rr] = pack_f16x2(u0.x, u0.y);
            ah[t][2 + rr] = pack_f16x2(u1.x, u1.y);
        }
#pragma unroll
        for (int nb = 0; nb < 4; ++nb) {
            uint32_t bh[4];
            uint32_t bo = (uint32_t)nb * 16 * BSTRB + ks * 32;
            ldsm4(bh, bbase + bo);
            float* c00 = acc + nb * 8;
            float* c01 = c00 + 4;
            float* c10 = acc + (4 + nb) * 8;
            float* c11 = c10 + 4;
            mma_f16(c00, ah[0], bh[0], bh[1]); mma_f16(c01, ah[0], bh[2], bh[3]);
            mma_f16(c10, ah[1], bh[0], bh[1]); mma_f16(c11, ah[1], bh[2], bh[3]);
        }
    }
}

__device__ __forceinline__ void frags_to_T(float* T, int wid, int lane, const float acc[64]) {
    int wr = wid & 3, wc = wid >> 2;
    int rbase = wr * 32 + (lane >> 2);
    int cb = wc * 64 + 2 * (lane & 3);
#pragma unroll
    for (int mrow = 0; mrow < 2; ++mrow) {
        int r0 = rbase + mrow * 16;
#pragma unroll
        for (int nb = 0; nb < 4; ++nb) {
#pragma unroll
            for (int t = 0; t < 2; ++t) {
                const float* a4 = acc + ((mrow * 4 + nb) * 2 + t) * 4;
                int c = cb + nb * 16 + t * 8;
                *reinterpret_cast<float2*>(T + r0 * TSTR + c) = make_float2(a4[0], a4[1]);
                *reinterpret_cast<float2*>(T + (r0 + 8) * TSTR + c) = make_float2(a4[2], a4[3]);
            }
        }
    }
}

// B preload: 30720 B contiguous (3 chunks)
__device__ __forceinline__ void issue_B(uint32_t smb, int tid, int half) {
    const char* src = (const char*)&g_Wf[half][0][0];
#pragma unroll
    for (int j = 0; j < 8; ++j) {
        int i = tid + 256 * j;
        if (i < 1920)
            cpa16(smb + BOFF + i * 16, src + i * 16, 16);
    }
}

// ---------------- 2: hc = W2 @ mean + b ----------------
__global__ __launch_bounds__(256, 2)
void hc_mma_kernel(const float* __restrict__ bias) {
    extern __shared__ __align__(16) char smem[];
    __shared__ float s_inv[128];
    uint32_t smb = smem_u32(smem);
    int tid = threadIdx.x, wid = tid >> 5, lane = tid & 31;
    int wr = wid & 3, wc = wid >> 2;
    int row0 = blockIdx.x * 128;
    const char* sbase = (const char*)g_sums + (size_t)row0 * 384;

    issue_B(smb, tid, 1);
#pragma unroll
    for (int j = 0; j < 4; ++j) {
        int i = tid + 256 * j, p = i >> 3, u = i & 7;
        cpa16(smb + p * ASTRB + u * 16, sbase + (size_t)p * 384 + u * 16, 16);
    }
    cpa_commit();
#pragma unroll
    for (int j = 0; j < 4; ++j) {
        int i = tid + 256 * j, p = i >> 3, u = i & 7;
        cpa16(smb + ABUF + p * ASTRB + u * 16, sbase + (size_t)p * 384 + 128 + u * 16, 16);
    }
    cpa_commit();

    if (tid < 128) {
        float c = g_sums[(size_t)(row0 + tid) * SUMS_STRIDE + 91];
        s_inv[tid] = (c > 0.f) ? 1.0f / c : 0.0f;
    }

    float acc[64];
#pragma unroll
    for (int j = 0; j < 64; ++j) acc[j] = 0.f;

    cpa_wait<1>();
    __syncthreads();
    float sv[4];
#pragma unroll
    for (int fr = 0; fr < 4; ++fr) sv[fr] = s_inv[wr * 32 + (lane >> 2) + fr * 8];

    compute_chunk<true>(smem, smb, 0, 0, wr, wc, lane, sv, acc);
    __syncthreads();
#pragma unroll
    for (int j = 0; j < 4; ++j) {
        int i = tid + 256 * j, p = i >> 3, u = i & 7;
        cpa16(smb + p * ASTRB + u * 16, sbase + (size_t)p * 384 + 256 + u * 16, 16);
    }
    cpa_commit();
    cpa_wait<1>();
    __syncthreads();
    compute_chunk<true>(smem, smb, ABUF, 1, wr, wc, lane, sv, acc);
    cpa_wait<0>();
    __syncthreads();
    compute_chunk<true>(smem, smb, 0, 2, wr, wc, lane, sv, acc);
    __syncthreads();

    float* T = reinterpret_cast<float*>(smem);
    frags_to_T(T, wid, lane, acc);
    __syncthreads();

    for (int i4 = tid; i4 < 4096; i4 += 256) {
        int p = i4 >> 5, c = (i4 & 31) * 4;
        float4 o = *reinterpret_cast<float4*>(T + p * TSTR + c);
        o.x += __ldg(bias + c + 0);
        o.y += __ldg(bias + c + 1);
        o.z += __ldg(bias + c + 2);
        o.w += __ldg(bias + c + 3);
        reinterpret_cast<float4*>(g_hc + (size_t)(row0 + p) * DOUT)[i4 & 31] = o;
    }
}

// ---------------- 3: main GEMM (profiled) ----------------
__global__ __launch_bounds__(256, 2)
void main_mma_kernel(const float* __restrict__ feat, const float* __restrict__ logit,
                     const float* __restrict__ pts, const float* __restrict__ proj) {
    extern __shared__ __align__(16) char smem[];
    uint32_t smb = smem_u32(smem);
    int tid = threadIdx.x, wid = tid >> 5, lane = tid & 31;
    int wr = wid & 3, wc = wid >> 2;
    int row0 = blockIdx.x * 128;

    // g0: B + A chunk0
    issue_B(smb, tid, 0);
#pragma unroll
    for (int j = 0; j < 4; ++j) {
        int i = tid + 256 * j, p = i >> 3, u = i & 7;
        int r = row0 + p;
        const char* s = (r < NPTS) ? (const char*)feat + (size_t)r * 256 + u * 16 : (const char*)feat;
        cpa16(smb + p * ASTRB + u * 16, s, (r < NPTS) ? 16u : 0u);
    }
    cpa_commit();
    // g1: A chunk1
#pragma unroll
    for (int j = 0; j < 4; ++j) {
        int i = tid + 256 * j, p = i >> 3, u = i & 7;
        int r = row0 + p;
        const char* s = (r < NPTS) ? (const char*)feat + (size_t)r * 256 + 128 + u * 16 : (const char*)feat;
        cpa16(smb + ABUF + p * ASTRB + u * 16, s, (r < NPTS) ? 16u : 0u);
    }
    cpa_commit();

    float acc[64];
#pragma unroll
    for (int j = 0; j < 64; ++j) acc[j] = 0.f;
    const float sv[4] = {1.f, 1.f, 1.f, 1.f};

    cpa_wait<1>();
    __syncthreads();
    compute_chunk<false>(smem, smb, 0, 0, wr, wc, lane, sv, acc);
    __syncthreads();

    // chunk2 into buf0: logit (5 units) + pts (1 unit) async; proj + zero tail scalar
#pragma unroll
    for (int j = 0; j < 3; ++j) {
        int i = tid + 256 * j, p = i / 6, u = i - p * 6;
        int r = row0 + p;
        const char* s;
        if (r < NPTS) s = (u < 5) ? (const char*)logit + (size_t)r * 80 + u * 16
                                  : (const char*)pts + (size_t)r * 16;
        else s = (const char*)feat;
        cpa16(smb + p * ASTRB + u * 16, s, (r < NPTS) ? 16u : 0u);
    }
    cpa_commit();
    {
        float* A0 = reinterpret_cast<float*>(smem);
#pragma unroll
        for (int j = 0; j < 4; ++j) {
            int i = tid + 256 * j, p = i >> 3, kk = i & 7;
            int r = row0 + p;
            float v = (kk < 3 && r < NPTS) ? proj[(size_t)r * 3 + kk] : 0.f;
            A0[p * 40 + 24 + kk] = v;
        }
    }
    cpa_wait<1>();
    __syncthreads();
    compute_chunk<false>(smem, smb, ABUF, 1, wr, wc, lane, sv, acc);
    cpa_wait<0>();
    __syncthreads();
    compute_chunk<false>(smem, smb, 0, 2, wr, wc, lane, sv, acc);
    __syncthreads();

    float* T = reinterpret_cast<float*>(smem);
    frags_to_T(T, wid, lane, acc);
    __syncthreads();

    // cooperative hc add: cs loaded HERE (not mainloop-live); two batches of 8 LDG.128
    {
        int p0 = wid * 16;
        int rl = row0 + p0 + (lane & 15);
        int csl = (rl < NPTS) ? g_cs[rl] : 0;
#pragma unroll
        for (int half = 0; half < 2; ++half) {
            float4 hv[8];
#pragma unroll
            for (int it = 0; it < 8; ++it) {
                int cs = __shfl_sync(0xFFFFFFFFu, csl, half * 8 + it);
                hv[it] = reinterpret_cast<const float4*>(g_hc + (size_t)cs * DOUT)[lane];
            }
#pragma unroll
            for (int it = 0; it < 8; ++it) {
                int p = p0 + half * 8 + it;
                if (row0 + p < NPTS) {
                    float4* q = reinterpret_cast<float4*>(T + p * TSTR + 4 * lane);
                    float4 t = *q;
                    t.x += hv[it].x; t.y += hv[it].y; t.z += hv[it].z; t.w += hv[it].w;
                    *q = t;
                }
            }
        }
    }
    __syncthreads();

    // BN partials: 2 threads per column, shfl-reduced -> ONE atomic per column per block
    {
        int c = tid >> 1, pg = tid & 1;
        float s = 0.f, q = 0.f;
#pragma unroll 8
        for (int p = pg * 64; p < pg * 64 + 64; ++p) {
            float v = T[p * TSTR + c];
            s += v; q += v * v;
        }
        s += __shfl_down_sync(0xFFFFFFFFu, s, 1);
        q += __shfl_down_sync(0xFFFFFFFFu, q, 1);
        if (!pg) { atomicAdd(&g_bnsum[c], s); atomicAdd(&g_bnsq[c], q); }
    }

    // coalesced fp16 g_hh store
    {
        int rem = NPTS - row0;
        for (int i4 = tid; i4 < 4096; i4 += 256) {
            int p = i4 >> 5, c4 = i4 & 31;
            if (p < rem) {
                float4 o = *reinterpret_cast<float4*>(T + p * TSTR + c4 * 4);
                __half2 h0 = __floats2half2_rn(o.x, o.y);
                __half2 h1 = __floats2half2_rn(o.z, o.w);
                uint2 st;
                st.x = *reinterpret_cast<uint32_t*>(&h0);
                st.y = *reinterpret_cast<uint32_t*>(&h1);
                reinterpret_cast<uint2*>(g_hh + ((size_t)(row0 + p) << 7))[c4] = st;
            }
        }
    }
}

// ---------------- 4: BN finalize ----------------
__global__ void bn_finalize_kernel(const float* __restrict__ gamma,
                                   const float* __restrict__ beta) {
    int d = threadIdx.x;
    const float invN = 1.0f / (float)NPTS;
    float mu = g_bnsum[d] * invN;
    float var = g_bnsq[d] * invN - mu * mu;
    if (var < 0.f) var = 0.f;
    float sc = gamma[d] * rsqrtf(var + EPS);
    g_scale[d] = sc;
    g_shift[d] = beta[d] - mu * sc;
}

// ---------------- 5: map ----------------
__global__ __launch_bounds__(256) void map_kernel(float* __restrict__ out) {
    __shared__ float sc[DOUT], sh[DOUT];
    int tid = threadIdx.x;
    if (tid < DOUT) { sc[tid] = g_scale[tid]; sh[tid] = g_shift[tid]; }
    __syncthreads();
    size_t gid = (size_t)blockIdx.x * 256 + tid;
    int d = ((int)(gid & 31)) * 4;
    uint2 raw = reinterpret_cast<const uint2*>(g_hh)[gid];
    float2 f0 = __half22float2(*reinterpret_cast<__half2*>(&raw.x));
    float2 f1 = __half22float2(*reinterpret_cast<__half2*>(&raw.y));
    float4 r;
    float v;
    v = f0.x * sc[d + 0] + sh[d + 0]; r.x = (v >= 0.f) ? v : SLOPE * v;
    v = f0.y * sc[d + 1] + sh[d + 1]; r.y = (v >= 0.f) ? v : SLOPE * v;
    v = f1.x * sc[d + 2] + sh[d + 2]; r.z = (v >= 0.f) ? v : SLOPE * v;
    v = f1.y * sc[d + 3] + sh[d + 3]; r.w = (v >= 0.f) ? v : SLOPE * v;
    reinterpret_cast<float4*>(out)[gid] = r;
}

// ---------------- launch ----------------
extern "C" void kernel_launch(void* const* d_in, const int* in_sizes, int n_in,
                              void* d_out, int out_size) {
    const float* points = (const float*)d_in[0];
    const float* proj   = (const float*)d_in[1];
    const float* feat   = (const float*)d_in[2];
    const float* logits = (const float*)d_in[3];
    const int*   idx    = (const int*)d_in[4];
    const void*  mask   = d_in[5];
    const float* W      = (const float*)d_in[6];
    const float* bias   = (const float*)d_in[7];
    const float* gamma  = (const float*)d_in[8];
    const float* beta   = (const float*)d_in[9];
    float* out = (float*)d_out;

    cudaFuncSetAttribute(hc_mma_kernel, cudaFuncAttributeMaxDynamicSharedMemorySize, SMEM_BYTES);
    cudaFuncSetAttribute(main_mma_kernel, cudaFuncAttributeMaxDynamicSharedMemorySize, SMEM_BYTES);

    prep_all_kernel<<<7500, 256>>>((const unsigned char*)mask, W);
    scatter_kernel<<<(NPTS + 255) / 256, 256>>>(feat, logits, points, proj, idx, mask);
    hc_mma_kernel<<<2 * NCLU / 128, 256, SMEM_BYTES>>>(bias);
    // launch 3 (profiled): main GEMM
    main_mma_kernel<<<NTILES, 256, SMEM_BYTES>>>(feat, logits, points, proj);
    bn_finalize_kernel<<<1, DOUT>>>(gamma, beta);
    map_kernel<<<62500, 256>>>(out);   // 16M uint2 / 256
}